// round 1
// baseline (speedup 1.0000x reference)
#include <cuda_runtime.h>
#include <cstdint>

#define NRAYS 16384
#define NFINE 128

// ---------------------------------------------------------------------------
// exact z-grid helpers (linspace values are exactly representable in fp32)
// ---------------------------------------------------------------------------
__device__ __forceinline__ float zlog_c(int i) {
    // segment 1 (i<128): (i-128)/128 ; segment 2: (i-128)/64
    return (i < 128) ? (float)(i - 128) * 0.0078125f : (float)(i - 128) * 0.015625f;
}
__device__ __forceinline__ float zmid_c(int i) {
    return 0.5f * (zlog_c(i) + zlog_c(i + 1));
}

__device__ __forceinline__ unsigned rotl32(unsigned x, int r) {
    return __funnelshift_l(x, x, r);
}

// JAX threefry2x32, key = jax.random.key(42) -> (0, 42).
// Partitionable mode (default in modern JAX): counts = iota(uint64);
// x0 = hi32(i) = 0 here, x1 = lo32(i); bits = out0 ^ out1.
__device__ __forceinline__ float tf_uniform(unsigned idx) {
    unsigned x0 = 0u, x1 = idx;
    const unsigned ks0 = 0u;
    const unsigned ks1 = 42u;
    const unsigned ks2 = 0u ^ 42u ^ 0x1BD11BDAu;
    x0 += ks0; x1 += ks1;
#define TF_RND(R) { x0 += x1; x1 = rotl32(x1, R); x1 ^= x0; }
    TF_RND(13) TF_RND(15) TF_RND(26) TF_RND(6)
    x0 += ks1; x1 += ks2 + 1u;
    TF_RND(17) TF_RND(29) TF_RND(16) TF_RND(24)
    x0 += ks2; x1 += ks0 + 2u;
    TF_RND(13) TF_RND(15) TF_RND(26) TF_RND(6)
    x0 += ks0; x1 += ks1 + 3u;
    TF_RND(17) TF_RND(29) TF_RND(16) TF_RND(24)
    x0 += ks1; x1 += ks2 + 4u;
    TF_RND(13) TF_RND(15) TF_RND(26) TF_RND(6)
    x0 += ks2; x1 += ks0 + 5u;
#undef TF_RND
    unsigned bits = x0 ^ x1;
    return __uint_as_float((bits >> 9) | 0x3f800000u) - 1.0f;
}

// jax.nn.softplus(x) = logaddexp(x, 0) = max(x,0) + log1p(exp(-|x|))
__device__ __forceinline__ float softplus_f(float x) {
    return fmaxf(x, 0.0f) + log1pf(expf(-fabsf(x)));
}

__device__ __forceinline__ void mip_scale(float& x, float& y, float& z) {
    float d = sqrtf(x * x + y * y + z * z);
    if (d > 1.0f) {
        float s = (2.0f - 1.0f / d) / d;
        x *= s; y *= s; z *= s;
    }
}

// ---------------------------------------------------------------------------
// fused kernel: 1 warp per ray, 4 warps / block
// ---------------------------------------------------------------------------
__global__ void __launch_bounds__(128) nerf_fused(
    const float* __restrict__ gh, const float* __restrict__ gw,
    const float* __restrict__ gK, const float* __restrict__ gE,
    const float* __restrict__ gbg,
    const float* __restrict__ gWd1, const float* __restrict__ gbd1,
    const float* __restrict__ gWd2, const float* __restrict__ gbd2,
    const float* __restrict__ gWc1, const float* __restrict__ gbc1,
    const float* __restrict__ gWc2, const float* __restrict__ gbc2,
    float* __restrict__ oImg, float* __restrict__ oW,
    float* __restrict__ oZ, float* __restrict__ oInv)
{
    __shared__ float sWd1[96], sBd1[32], sWd2[32], sBd2[1];
    __shared__ float sWc1[1120], sBc1[32], sWc2[96], sBc2[3];
    __shared__ float sCdf[4][192];

    const int tid = threadIdx.x;
    for (int i = tid; i < 1120; i += 128) sWc1[i] = gWc1[i];
    for (int i = tid; i < 96; i += 128) { sWd1[i] = gWd1[i]; sWc2[i] = gWc2[i]; }
    if (tid < 32) { sBd1[tid] = gbd1[tid]; sWd2[tid] = gWd2[tid]; sBc1[tid] = gbc1[tid]; }
    if (tid == 32) sBd2[0] = gbd2[0];
    if (tid < 3)   sBc2[tid] = gbc2[tid];
    __syncthreads();

    const int lane = tid & 31;
    const int warp = tid >> 5;
    const int ray  = (blockIdx.x << 2) + warp;
    if (ray >= NRAYS) return;

    // ---- ray setup (redundant per lane; cheap) ----
    float k00 = gK[0], k01 = gK[1], k02 = gK[2];
    float k10 = gK[3], k11 = gK[4], k12 = gK[5];
    float k20 = gK[6], k21 = gK[7], k22 = gK[8];
    float det = k00 * (k11 * k22 - k12 * k21)
              + k01 * (k12 * k20 - k10 * k22)
              + k02 * (k10 * k21 - k11 * k20);
    float id = 1.0f / det;
    float i00 = (k11 * k22 - k12 * k21) * id, i01 = (k02 * k21 - k01 * k22) * id, i02 = (k01 * k12 - k02 * k11) * id;
    float i10 = (k12 * k20 - k10 * k22) * id, i11 = (k00 * k22 - k02 * k20) * id, i12 = (k02 * k10 - k00 * k12) * id;
    float i20 = (k10 * k21 - k11 * k20) * id, i21 = (k01 * k20 - k00 * k21) * id, i22 = (k00 * k11 - k01 * k10) * id;

    float dvx = gw[ray] + 0.5f, dvy = gh[ray] + 0.5f, dvz = 1.0f;
    // cam = dirs @ inv(K)^T
    float cx = dvx * i00 + dvy * i01 + dvz * i02;
    float cy = dvx * i10 + dvy * i11 + dvz * i12;
    float cz = dvx * i20 + dvy * i21 + dvz * i22;

    const float* Er = gE + (size_t)ray * 16;
    float ox = Er[3], oy = Er[7], oz = Er[11];
    float rdx = Er[0] * cx + Er[1] * cy + Er[2]  * cz;
    float rdy = Er[4] * cx + Er[5] * cy + Er[6]  * cz;
    float rdz = Er[8] * cx + Er[9] * cy + Er[10] * cz;
    float rn  = sqrtf(rdx * rdx + rdy * rdy + rdz * rdz);
    float ndx = rdx / rn, ndy = rdy / rn, ndz = rdz / rn;

    // ---- coarse pass: 6 contiguous samples per lane, density-only MLP ----
    float alpha[6];
    const float bd2v = sBd2[0];
#pragma unroll
    for (int p = 0; p < 3; ++p) {
        const int s0 = lane * 6 + 2 * p;
        float zl0 = zlog_c(s0), zl1 = zlog_c(s0 + 1);
        float z0 = exp10f(zl0), z1 = exp10f(zl1);
        float px0 = fmaf(rdx, z0, ox), py0 = fmaf(rdy, z0, oy), pz0 = fmaf(rdz, z0, oz);
        float px1 = fmaf(rdx, z1, ox), py1 = fmaf(rdy, z1, oy), pz1 = fmaf(rdz, z1, oz);
        mip_scale(px0, py0, pz0);
        mip_scale(px1, py1, pz1);
        float sg0 = bd2v, sg1 = bd2v;
#pragma unroll 4
        for (int c = 0; c < 32; ++c) {
            float w0 = sWd1[c], w1 = sWd1[32 + c], w2 = sWd1[64 + c];
            float bb = sBd1[c], v2 = sWd2[c];
            float t0 = fmaf(px0, w0, fmaf(py0, w1, fmaf(pz0, w2, bb)));
            float t1 = fmaf(px1, w0, fmaf(py1, w1, fmaf(pz1, w2, bb)));
            t0 = fmaxf(t0, 0.0f); t1 = fmaxf(t1, 0.0f);
            sg0 = fmaf(t0, v2, sg0); sg1 = fmaf(t1, v2, sg1);
        }
        float si0 = softplus_f(sg0), si1 = softplus_f(sg1);
        float d0 = (s0     < 128) ? 0.0078125f : ((s0     < 191) ? 0.015625f : 0.0f);
        float d1 = (s0 + 1 < 128) ? 0.0078125f : ((s0 + 1 < 191) ? 0.015625f : 0.0f);
        alpha[2 * p]     = 1.0f - expf(-si0 * d0);
        alpha[2 * p + 1] = 1.0f - expf(-si1 * d1);
    }

    // ---- transmittance weights (warp multiplicative scan) ----
    float om[6]; float lprod = 1.0f;
#pragma unroll
    for (int q = 0; q < 6; ++q) { om[q] = 1.0f - alpha[q]; lprod *= om[q]; }
    float scanp = lprod;
#pragma unroll
    for (int o = 1; o < 32; o <<= 1) {
        float t = __shfl_up_sync(0xffffffffu, scanp, o);
        if (lane >= o) scanp *= t;
    }
    float T = __shfl_up_sync(0xffffffffu, scanp, 1);
    if (lane == 0) T = 1.0f;
    float wgt[6];
#pragma unroll
    for (int q = 0; q < 6; ++q) { wgt[q] = alpha[q] * T; T *= om[q]; }

    // ---- reweight ----
    float wprev = __shfl_up_sync(0xffffffffu, wgt[5], 1);   if (lane == 0)  wprev = 0.0f;
    float wnext = __shfl_down_sync(0xffffffffu, wgt[0], 1); if (lane == 31) wnext = 0.0f;
    float wr[6]; float lsum = 0.0f;
#pragma unroll
    for (int q = 0; q < 6; ++q) {
        float wm = (q == 0) ? wprev : wgt[q - 1];
        float wp = (q == 5) ? wnext : wgt[q + 1];
        float v = 0.5f * (fmaxf(wm, wgt[q]) + fmaxf(wgt[q], wp)) + (float)(0.02 / 192.0);
        int s = lane * 6 + q;
        v *= (s < 128) ? (float)(128.0 / 192.0) : (float)(64.0 / 192.0);
        wr[q] = v; lsum += v;
    }
    float tot = lsum;
#pragma unroll
    for (int o = 16; o; o >>= 1) tot += __shfl_xor_sync(0xffffffffu, tot, o);

    float wn[6]; float ls2 = 0.0f;
#pragma unroll
    for (int q = 0; q < 6; ++q) { wn[q] = wr[q] / tot; ls2 += wn[q]; }
    float scs = ls2;
#pragma unroll
    for (int o = 1; o < 32; o <<= 1) {
        float t = __shfl_up_sync(0xffffffffu, scs, o);
        if (lane >= o) scs += t;
    }
    float base = __shfl_up_sync(0xffffffffu, scs, 1);
    if (lane == 0) base = 0.0f;
    float run = base;
#pragma unroll
    for (int q = 0; q < 6; ++q) { run += wn[q]; sCdf[warp][lane * 6 + q] = run; }
    __syncwarp();

    const float cdfl = sCdf[warp][1];
    const float cdfh = sCdf[warp][190];

    // ---- importance sampling: 4 fine samples per lane ----
    float zlf[4], zf[4];
#pragma unroll
    for (int q = 0; q < 4; ++q) {
        int j = (lane << 2) + q;
        float r = tf_uniform((unsigned)(ray * NFINE + j));
        float u = (float)j * 0.0078125f + r * 0.0078125f;
        u = u * (cdfh - cdfl) + cdfl;
        int lo = 0, hi = 189;
        while (lo < hi) {
            int mid = (lo + hi) >> 1;
            if (sCdf[warp][1 + mid] <= u) lo = mid + 1; else hi = mid;
        }
        int ind = lo + 1;                      // in [1, 190]
        float cb = sCdf[warp][ind - 1], ca = sCdf[warp][ind];
        float tt = (u - cb) / (ca - cb);
        float zb = zmid_c(ind - 1), za = zmid_c(ind);
        zlf[q] = zb + (za - zb) * tt;
        zf[q]  = exp10f(zlf[q]);
    }

    // ---- fine pass: density + color MLP, 2-sample register blocking ----
    float sig[4], rr[4], rg[4], rb[4];
#pragma unroll
    for (int p = 0; p < 2; ++p) {
        const int q0 = 2 * p, q1 = 2 * p + 1;
        float px0 = fmaf(rdx, zf[q0], ox), py0 = fmaf(rdy, zf[q0], oy), pz0 = fmaf(rdz, zf[q0], oz);
        float px1 = fmaf(rdx, zf[q1], ox), py1 = fmaf(rdy, zf[q1], oy), pz1 = fmaf(rdz, zf[q1], oz);
        mip_scale(px0, py0, pz0);
        mip_scale(px1, py1, pz1);

        float f0[35], f1[35];
        f0[32] = ndx; f0[33] = ndy; f0[34] = ndz;
        f1[32] = ndx; f1[33] = ndy; f1[34] = ndz;
        float sg0 = bd2v, sg1 = bd2v;
#pragma unroll
        for (int c = 0; c < 32; ++c) {
            float w0 = sWd1[c], w1 = sWd1[32 + c], w2 = sWd1[64 + c];
            float bb = sBd1[c], v2 = sWd2[c];
            float t0 = fmaf(px0, w0, fmaf(py0, w1, fmaf(pz0, w2, bb)));
            float t1 = fmaf(px1, w0, fmaf(py1, w1, fmaf(pz1, w2, bb)));
            t0 = fmaxf(t0, 0.0f); t1 = fmaxf(t1, 0.0f);
            f0[c] = t0; f1[c] = t1;
            sg0 = fmaf(t0, v2, sg0); sg1 = fmaf(t1, v2, sg1);
        }
        sig[q0] = softplus_f(sg0);
        sig[q1] = softplus_f(sg1);

        float a0r = sBc2[0], a0g = sBc2[1], a0b = sBc2[2];
        float a1r = sBc2[0], a1g = sBc2[1], a1b = sBc2[2];
#pragma unroll 2
        for (int c = 0; c < 32; ++c) {
            float bb = sBc1[c];
            float acc0 = bb, acc1 = bb;
#pragma unroll
            for (int k = 0; k < 35; ++k) {
                float wv = sWc1[k * 32 + c];
                acc0 = fmaf(f0[k], wv, acc0);
                acc1 = fmaf(f1[k], wv, acc1);
            }
            acc0 = fmaxf(acc0, 0.0f); acc1 = fmaxf(acc1, 0.0f);
            float u0 = sWc2[c * 3 + 0], u1 = sWc2[c * 3 + 1], u2 = sWc2[c * 3 + 2];
            a0r = fmaf(acc0, u0, a0r); a0g = fmaf(acc0, u1, a0g); a0b = fmaf(acc0, u2, a0b);
            a1r = fmaf(acc1, u0, a1r); a1g = fmaf(acc1, u1, a1g); a1b = fmaf(acc1, u2, a1b);
        }
        rr[q0] = 1.0f / (1.0f + expf(-a0r));
        rg[q0] = 1.0f / (1.0f + expf(-a0g));
        rb[q0] = 1.0f / (1.0f + expf(-a0b));
        rr[q1] = 1.0f / (1.0f + expf(-a1r));
        rg[q1] = 1.0f / (1.0f + expf(-a1g));
        rb[q1] = 1.0f / (1.0f + expf(-a1b));
    }

    // ---- fine weights + accumulation ----
    float znx = __shfl_down_sync(0xffffffffu, zlf[0], 1);
    float dl[4];
    dl[0] = zlf[1] - zlf[0];
    dl[1] = zlf[2] - zlf[1];
    dl[2] = zlf[3] - zlf[2];
    dl[3] = (lane == 31) ? 0.0f : (znx - zlf[3]);

    float al[4], om2[4]; float lp = 1.0f;
#pragma unroll
    for (int q = 0; q < 4; ++q) {
        al[q] = 1.0f - expf(-sig[q] * dl[q]);
        om2[q] = 1.0f - al[q];
        lp *= om2[q];
    }
    float scan2 = lp;
#pragma unroll
    for (int o = 1; o < 32; o <<= 1) {
        float t = __shfl_up_sync(0xffffffffu, scan2, o);
        if (lane >= o) scan2 *= t;
    }
    float T2 = __shfl_up_sync(0xffffffffu, scan2, 1);
    if (lane == 0) T2 = 1.0f;
    float w4[4];
#pragma unroll
    for (int q = 0; q < 4; ++q) { w4[q] = al[q] * T2; T2 *= om2[q]; }

    float ir = 0.0f, ig = 0.0f, ib = 0.0f, ivd = 0.0f, ws = 0.0f;
#pragma unroll
    for (int q = 0; q < 4; ++q) {
        ir = fmaf(w4[q], rr[q], ir);
        ig = fmaf(w4[q], rg[q], ig);
        ib = fmaf(w4[q], rb[q], ib);
        ivd += w4[q] / zf[q];
        ws  += w4[q];
    }
#pragma unroll
    for (int o = 16; o; o >>= 1) {
        ir  += __shfl_xor_sync(0xffffffffu, ir, o);
        ig  += __shfl_xor_sync(0xffffffffu, ig, o);
        ib  += __shfl_xor_sync(0xffffffffu, ib, o);
        ivd += __shfl_xor_sync(0xffffffffu, ivd, o);
        ws  += __shfl_xor_sync(0xffffffffu, ws, o);
    }

    // ---- stores ----
    float4 wv4 = make_float4(w4[0], w4[1], w4[2], w4[3]);
    *(float4*)(oW + (size_t)ray * NFINE + lane * 4) = wv4;
    float4 zv4 = make_float4((zlf[0] + 1.0f) * 0.5f, (zlf[1] + 1.0f) * 0.5f,
                             (zlf[2] + 1.0f) * 0.5f, (zlf[3] + 1.0f) * 0.5f);
    *(float4*)(oZ + (size_t)ray * NFINE + lane * 4) = zv4;

    if (lane == 0) {
        float oneMw = 1.0f - ws;
        oImg[ray * 3 + 0] = ir + oneMw * gbg[0];
        oImg[ray * 3 + 1] = ig + oneMw * gbg[1];
        oImg[ray * 3 + 2] = ib + oneMw * gbg[2];
        oInv[ray] = ivd;
    }
}

// ---------------------------------------------------------------------------
// launch: inputs per metadata order:
// 0:n(int,unused) 1:h 2:w 3:K 4:E 5:bg 6:Wd1 7:bd1 8:Wd2 9:bd2 10:Wc1 11:bc1 12:Wc2 13:bc2
// output: image[N*3] | weights[N*128] | z_log_s[N*128] | invdepth[N]
// ---------------------------------------------------------------------------
extern "C" void kernel_launch(void* const* d_in, const int* in_sizes, int n_in,
                              void* d_out, int out_size) {
    const float* h   = (const float*)d_in[1];
    const float* w   = (const float*)d_in[2];
    const float* K   = (const float*)d_in[3];
    const float* E   = (const float*)d_in[4];
    const float* bg  = (const float*)d_in[5];
    const float* Wd1 = (const float*)d_in[6];
    const float* bd1 = (const float*)d_in[7];
    const float* Wd2 = (const float*)d_in[8];
    const float* bd2 = (const float*)d_in[9];
    const float* Wc1 = (const float*)d_in[10];
    const float* bc1 = (const float*)d_in[11];
    const float* Wc2 = (const float*)d_in[12];
    const float* bc2 = (const float*)d_in[13];

    float* out   = (float*)d_out;
    float* oImg  = out;                               // 16384*3
    float* oW    = out + NRAYS * 3;                   // 16384*128
    float* oZ    = oW + (size_t)NRAYS * NFINE;        // 16384*128
    float* oInv  = oZ + (size_t)NRAYS * NFINE;        // 16384

    nerf_fused<<<NRAYS / 4, 128>>>(h, w, K, E, bg,
                                   Wd1, bd1, Wd2, bd2,
                                   Wc1, bc1, Wc2, bc2,
                                   oImg, oW, oZ, oInv);
}

// round 2
// speedup vs baseline: 1.9983x; 1.9983x over previous
#include <cuda_runtime.h>
#include <cstdint>

#define NRAYS 16384
#define NFINE 128

// exact z-grid helpers (linspace values exactly representable in fp32)
__device__ __forceinline__ float zlog_c(int i) {
    return (i < 128) ? (float)(i - 128) * 0.0078125f : (float)(i - 128) * 0.015625f;
}
__device__ __forceinline__ float zmid_c(int i) {
    return 0.5f * (zlog_c(i) + zlog_c(i + 1));
}

__device__ __forceinline__ unsigned rotl32(unsigned x, int r) {
    return __funnelshift_l(x, x, r);
}

// JAX threefry2x32, key=(0,42), partitionable counter mode: bits = out0^out1
__device__ __forceinline__ float tf_uniform(unsigned idx) {
    unsigned x0 = 0u, x1 = idx;
    const unsigned ks1 = 42u;
    const unsigned ks2 = 42u ^ 0x1BD11BDAu;
    x0 += 0u; x1 += ks1;
#define TF_RND(R) { x0 += x1; x1 = rotl32(x1, R); x1 ^= x0; }
    TF_RND(13) TF_RND(15) TF_RND(26) TF_RND(6)
    x0 += ks1; x1 += ks2 + 1u;
    TF_RND(17) TF_RND(29) TF_RND(16) TF_RND(24)
    x0 += ks2; x1 += 0u + 2u;
    TF_RND(13) TF_RND(15) TF_RND(26) TF_RND(6)
    x0 += 0u; x1 += ks1 + 3u;
    TF_RND(17) TF_RND(29) TF_RND(16) TF_RND(24)
    x0 += ks1; x1 += ks2 + 4u;
    TF_RND(13) TF_RND(15) TF_RND(26) TF_RND(6)
    x0 += ks2; x1 += 0u + 5u;
#undef TF_RND
    unsigned bits = x0 ^ x1;
    return __uint_as_float((bits >> 9) | 0x3f800000u) - 1.0f;
}

__device__ __forceinline__ float softplus_f(float x) {
    return fmaxf(x, 0.0f) + log1pf(expf(-fabsf(x)));
}

__device__ __forceinline__ void mip_scale(float& x, float& y, float& z) {
    float d = sqrtf(x * x + y * y + z * z);
    if (d > 1.0f) {
        float s = (2.0f - 1.0f / d) / d;
        x *= s; y *= s; z *= s;
    }
}

__global__ void __launch_bounds__(128, 3) nerf_fused(
    const float* __restrict__ gh, const float* __restrict__ gw,
    const float* __restrict__ gK, const float* __restrict__ gE,
    const float* __restrict__ gbg,
    const float* __restrict__ gWd1, const float* __restrict__ gbd1,
    const float* __restrict__ gWd2, const float* __restrict__ gbd2,
    const float* __restrict__ gWc1, const float* __restrict__ gbc1,
    const float* __restrict__ gWc2, const float* __restrict__ gbc2,
    float* __restrict__ oImg, float* __restrict__ oW,
    float* __restrict__ oZ, float* __restrict__ oInv)
{
    __shared__ float4 sWd1p[32];                      // (w0,w1,w2,b) per hidden c
    __shared__ float  sWd2[32];
    __shared__ __align__(16) float sWc1[1120];        // [35][32] row-major
    __shared__ __align__(16) float sBc1[32];
    __shared__ __align__(16) float sWc2c[3][32];      // column-major Wc2
    __shared__ float sCdf[4][192];

    const int tid = threadIdx.x;
    for (int i = tid; i < 1120; i += 128) sWc1[i] = gWc1[i];
    if (tid < 32) {
        sWd1p[tid] = make_float4(gWd1[tid], gWd1[32 + tid], gWd1[64 + tid], gbd1[tid]);
        sWd2[tid]  = gWd2[tid];
        sBc1[tid]  = gbc1[tid];
        sWc2c[0][tid] = gWc2[tid * 3 + 0];
        sWc2c[1][tid] = gWc2[tid * 3 + 1];
        sWc2c[2][tid] = gWc2[tid * 3 + 2];
    }
    __syncthreads();

    const int lane = tid & 31;
    const int warp = tid >> 5;
    const int ray  = (blockIdx.x << 2) + warp;

    // ---- ray setup ----
    float k00 = gK[0], k01 = gK[1], k02 = gK[2];
    float k10 = gK[3], k11 = gK[4], k12 = gK[5];
    float k20 = gK[6], k21 = gK[7], k22 = gK[8];
    float det = k00 * (k11 * k22 - k12 * k21)
              + k01 * (k12 * k20 - k10 * k22)
              + k02 * (k10 * k21 - k11 * k20);
    float id = 1.0f / det;
    float i00 = (k11 * k22 - k12 * k21) * id, i01 = (k02 * k21 - k01 * k22) * id, i02 = (k01 * k12 - k02 * k11) * id;
    float i10 = (k12 * k20 - k10 * k22) * id, i11 = (k00 * k22 - k02 * k20) * id, i12 = (k02 * k10 - k00 * k12) * id;
    float i20 = (k10 * k21 - k11 * k20) * id, i21 = (k01 * k20 - k00 * k21) * id, i22 = (k00 * k11 - k01 * k10) * id;

    float dvx = gw[ray] + 0.5f, dvy = gh[ray] + 0.5f;
    float cx = dvx * i00 + dvy * i01 + i02;
    float cy = dvx * i10 + dvy * i11 + i12;
    float cz = dvx * i20 + dvy * i21 + i22;

    const float* Er = gE + (size_t)ray * 16;
    float ox = Er[3], oy = Er[7], oz = Er[11];
    float rdx = Er[0] * cx + Er[1] * cy + Er[2]  * cz;
    float rdy = Er[4] * cx + Er[5] * cy + Er[6]  * cz;
    float rdz = Er[8] * cx + Er[9] * cy + Er[10] * cz;
    float rn  = rsqrtf(rdx * rdx + rdy * rdy + rdz * rdz) ;
    // match jnp: d / ||d|| ; use exact division
    rn = sqrtf(rdx * rdx + rdy * rdy + rdz * rdz);
    float ndx = rdx / rn, ndy = rdy / rn, ndz = rdz / rn;

    const float bd2v = gbd2[0];
    const float bc2x = gbc2[0], bc2y = gbc2[1], bc2z = gbc2[2];

    // ---- coarse pass: 6 samples/lane, density MLP only ----
    float alpha[6];
#pragma unroll
    for (int p = 0; p < 3; ++p) {
        const int s0 = lane * 6 + 2 * p;
        float zl0 = zlog_c(s0), zl1 = zlog_c(s0 + 1);
        float z0 = exp10f(zl0), z1 = exp10f(zl1);
        float px0 = fmaf(rdx, z0, ox), py0 = fmaf(rdy, z0, oy), pz0 = fmaf(rdz, z0, oz);
        float px1 = fmaf(rdx, z1, ox), py1 = fmaf(rdy, z1, oy), pz1 = fmaf(rdz, z1, oz);
        mip_scale(px0, py0, pz0);
        mip_scale(px1, py1, pz1);
        float sg0 = bd2v, sg1 = bd2v;
#pragma unroll 4
        for (int c = 0; c < 32; ++c) {
            float4 wd = sWd1p[c];
            float v2 = sWd2[c];
            float t0 = fmaf(px0, wd.x, fmaf(py0, wd.y, fmaf(pz0, wd.z, wd.w)));
            float t1 = fmaf(px1, wd.x, fmaf(py1, wd.y, fmaf(pz1, wd.z, wd.w)));
            t0 = fmaxf(t0, 0.0f); t1 = fmaxf(t1, 0.0f);
            sg0 = fmaf(t0, v2, sg0); sg1 = fmaf(t1, v2, sg1);
        }
        float si0 = softplus_f(sg0), si1 = softplus_f(sg1);
        float d0 = (s0     < 128) ? 0.0078125f : ((s0     < 191) ? 0.015625f : 0.0f);
        float d1 = (s0 + 1 < 128) ? 0.0078125f : ((s0 + 1 < 191) ? 0.015625f : 0.0f);
        alpha[2 * p]     = 1.0f - expf(-si0 * d0);
        alpha[2 * p + 1] = 1.0f - expf(-si1 * d1);
    }

    // ---- transmittance weights (warp multiplicative scan) ----
    float om[6]; float lprod = 1.0f;
#pragma unroll
    for (int q = 0; q < 6; ++q) { om[q] = 1.0f - alpha[q]; lprod *= om[q]; }
    float scanp = lprod;
#pragma unroll
    for (int o = 1; o < 32; o <<= 1) {
        float t = __shfl_up_sync(0xffffffffu, scanp, o);
        if (lane >= o) scanp *= t;
    }
    float T = __shfl_up_sync(0xffffffffu, scanp, 1);
    if (lane == 0) T = 1.0f;
    float wgt[6];
#pragma unroll
    for (int q = 0; q < 6; ++q) { wgt[q] = alpha[q] * T; T *= om[q]; }

    // ---- reweight ----
    float wprev = __shfl_up_sync(0xffffffffu, wgt[5], 1);   if (lane == 0)  wprev = 0.0f;
    float wnext = __shfl_down_sync(0xffffffffu, wgt[0], 1); if (lane == 31) wnext = 0.0f;
    float wr[6]; float lsum = 0.0f;
#pragma unroll
    for (int q = 0; q < 6; ++q) {
        float wm = (q == 0) ? wprev : wgt[q - 1];
        float wp = (q == 5) ? wnext : wgt[q + 1];
        float v = 0.5f * (fmaxf(wm, wgt[q]) + fmaxf(wgt[q], wp)) + (float)(0.02 / 192.0);
        int s = lane * 6 + q;
        v *= (s < 128) ? (float)(128.0 / 192.0) : (float)(64.0 / 192.0);
        wr[q] = v; lsum += v;
    }
    float tot = lsum;
#pragma unroll
    for (int o = 16; o; o >>= 1) tot += __shfl_xor_sync(0xffffffffu, tot, o);

    float wn[6]; float ls2 = 0.0f;
#pragma unroll
    for (int q = 0; q < 6; ++q) { wn[q] = wr[q] / tot; ls2 += wn[q]; }
    float scs = ls2;
#pragma unroll
    for (int o = 1; o < 32; o <<= 1) {
        float t = __shfl_up_sync(0xffffffffu, scs, o);
        if (lane >= o) scs += t;
    }
    float base = __shfl_up_sync(0xffffffffu, scs, 1);
    if (lane == 0) base = 0.0f;
    float run = base;
#pragma unroll
    for (int q = 0; q < 6; ++q) { run += wn[q]; sCdf[warp][lane * 6 + q] = run; }
    __syncwarp();

    const float cdfl = sCdf[warp][1];
    const float cdfh = sCdf[warp][190];

    // ---- importance sampling: branchless bit-ladder searchsorted ----
    float zlf[4];
#pragma unroll
    for (int q = 0; q < 4; ++q) {
        int j = (lane << 2) + q;
        float r = tf_uniform((unsigned)(ray * NFINE + j));
        float u = (float)j * 0.0078125f + r * 0.0078125f;
        u = u * (cdfh - cdfl) + cdfl;
        int k = 0;
#pragma unroll
        for (int s = 128; s >= 1; s >>= 1) {
            int cand = k + s;
            if (cand <= 189 && sCdf[warp][cand] <= u) k = cand;
        }
        float cb = sCdf[warp][k], ca = sCdf[warp][k + 1];
        float tt = (u - cb) / (ca - cb);
        float zb = zmid_c(k), za = zmid_c(k + 1);
        zlf[q] = zb + (za - zb) * tt;
    }

    // ---- fine pass: streamed features (density L1 fused into color L1) ----
    float sig[4], rr[4], rg[4], rb[4];
#pragma unroll
    for (int p = 0; p < 2; ++p) {
        const int q0 = 2 * p, q1 = 2 * p + 1;
        float z0 = exp10f(zlf[q0]), z1 = exp10f(zlf[q1]);
        float px0 = fmaf(rdx, z0, ox), py0 = fmaf(rdy, z0, oy), pz0 = fmaf(rdz, z0, oz);
        float px1 = fmaf(rdx, z1, ox), py1 = fmaf(rdy, z1, oy), pz1 = fmaf(rdz, z1, oz);
        mip_scale(px0, py0, pz0);
        mip_scale(px1, py1, pz1);

        // color layer1 accumulators, init = bc1 + dir terms (rows 32..34 of Wc1)
        float acc0[32], acc1[32];
#pragma unroll
        for (int j4 = 0; j4 < 32; j4 += 4) {
            float4 b  = *(const float4*)&sBc1[j4];
            float4 wx = *(const float4*)&sWc1[1024 + j4];
            float4 wy = *(const float4*)&sWc1[1056 + j4];
            float4 wz = *(const float4*)&sWc1[1088 + j4];
            float v0 = fmaf(ndx, wx.x, fmaf(ndy, wy.x, fmaf(ndz, wz.x, b.x)));
            float v1 = fmaf(ndx, wx.y, fmaf(ndy, wy.y, fmaf(ndz, wz.y, b.y)));
            float v2 = fmaf(ndx, wx.z, fmaf(ndy, wy.z, fmaf(ndz, wz.z, b.z)));
            float v3 = fmaf(ndx, wx.w, fmaf(ndy, wy.w, fmaf(ndz, wz.w, b.w)));
            acc0[j4 + 0] = v0; acc1[j4 + 0] = v0;
            acc0[j4 + 1] = v1; acc1[j4 + 1] = v1;
            acc0[j4 + 2] = v2; acc1[j4 + 2] = v2;
            acc0[j4 + 3] = v3; acc1[j4 + 3] = v3;
        }

        float sg0 = bd2v, sg1 = bd2v;
#pragma unroll 2
        for (int c = 0; c < 32; ++c) {
            float4 wd = sWd1p[c];
            float v2 = sWd2[c];
            float t0 = fmaf(px0, wd.x, fmaf(py0, wd.y, fmaf(pz0, wd.z, wd.w)));
            float t1 = fmaf(px1, wd.x, fmaf(py1, wd.y, fmaf(pz1, wd.z, wd.w)));
            t0 = fmaxf(t0, 0.0f); t1 = fmaxf(t1, 0.0f);
            sg0 = fmaf(t0, v2, sg0); sg1 = fmaf(t1, v2, sg1);
            const float4* wc = (const float4*)&sWc1[c * 32];
#pragma unroll
            for (int j4 = 0; j4 < 8; ++j4) {
                float4 wv = wc[j4];
                acc0[4 * j4 + 0] = fmaf(t0, wv.x, acc0[4 * j4 + 0]);
                acc1[4 * j4 + 0] = fmaf(t1, wv.x, acc1[4 * j4 + 0]);
                acc0[4 * j4 + 1] = fmaf(t0, wv.y, acc0[4 * j4 + 1]);
                acc1[4 * j4 + 1] = fmaf(t1, wv.y, acc1[4 * j4 + 1]);
                acc0[4 * j4 + 2] = fmaf(t0, wv.z, acc0[4 * j4 + 2]);
                acc1[4 * j4 + 2] = fmaf(t1, wv.z, acc1[4 * j4 + 2]);
                acc0[4 * j4 + 3] = fmaf(t0, wv.w, acc0[4 * j4 + 3]);
                acc1[4 * j4 + 3] = fmaf(t1, wv.w, acc1[4 * j4 + 3]);
            }
        }
        sig[q0] = softplus_f(sg0);
        sig[q1] = softplus_f(sg1);

        // color layer2
        float a0r = bc2x, a0g = bc2y, a0b = bc2z;
        float a1r = bc2x, a1g = bc2y, a1b = bc2z;
#pragma unroll
        for (int j4 = 0; j4 < 32; j4 += 4) {
            float4 u0 = *(const float4*)&sWc2c[0][j4];
            float4 u1 = *(const float4*)&sWc2c[1][j4];
            float4 u2 = *(const float4*)&sWc2c[2][j4];
            float h00 = fmaxf(acc0[j4 + 0], 0.0f), h10 = fmaxf(acc1[j4 + 0], 0.0f);
            float h01 = fmaxf(acc0[j4 + 1], 0.0f), h11 = fmaxf(acc1[j4 + 1], 0.0f);
            float h02 = fmaxf(acc0[j4 + 2], 0.0f), h12 = fmaxf(acc1[j4 + 2], 0.0f);
            float h03 = fmaxf(acc0[j4 + 3], 0.0f), h13 = fmaxf(acc1[j4 + 3], 0.0f);
            a0r = fmaf(h00, u0.x, a0r); a0g = fmaf(h00, u1.x, a0g); a0b = fmaf(h00, u2.x, a0b);
            a1r = fmaf(h10, u0.x, a1r); a1g = fmaf(h10, u1.x, a1g); a1b = fmaf(h10, u2.x, a1b);
            a0r = fmaf(h01, u0.y, a0r); a0g = fmaf(h01, u1.y, a0g); a0b = fmaf(h01, u2.y, a0b);
            a1r = fmaf(h11, u0.y, a1r); a1g = fmaf(h11, u1.y, a1g); a1b = fmaf(h11, u2.y, a1b);
            a0r = fmaf(h02, u0.z, a0r); a0g = fmaf(h02, u1.z, a0g); a0b = fmaf(h02, u2.z, a0b);
            a1r = fmaf(h12, u0.z, a1r); a1g = fmaf(h12, u1.z, a1g); a1b = fmaf(h12, u2.z, a1b);
            a0r = fmaf(h03, u0.w, a0r); a0g = fmaf(h03, u1.w, a0g); a0b = fmaf(h03, u2.w, a0b);
            a1r = fmaf(h13, u0.w, a1r); a1g = fmaf(h13, u1.w, a1g); a1b = fmaf(h13, u2.w, a1b);
        }
        rr[q0] = 1.0f / (1.0f + expf(-a0r));
        rg[q0] = 1.0f / (1.0f + expf(-a0g));
        rb[q0] = 1.0f / (1.0f + expf(-a0b));
        rr[q1] = 1.0f / (1.0f + expf(-a1r));
        rg[q1] = 1.0f / (1.0f + expf(-a1g));
        rb[q1] = 1.0f / (1.0f + expf(-a1b));
    }

    // ---- fine weights + accumulation ----
    float znx = __shfl_down_sync(0xffffffffu, zlf[0], 1);
    float dl[4];
    dl[0] = zlf[1] - zlf[0];
    dl[1] = zlf[2] - zlf[1];
    dl[2] = zlf[3] - zlf[2];
    dl[3] = (lane == 31) ? 0.0f : (znx - zlf[3]);

    float al[4], om2[4]; float lp = 1.0f;
#pragma unroll
    for (int q = 0; q < 4; ++q) {
        al[q] = 1.0f - expf(-sig[q] * dl[q]);
        om2[q] = 1.0f - al[q];
        lp *= om2[q];
    }
    float scan2 = lp;
#pragma unroll
    for (int o = 1; o < 32; o <<= 1) {
        float t = __shfl_up_sync(0xffffffffu, scan2, o);
        if (lane >= o) scan2 *= t;
    }
    float T2 = __shfl_up_sync(0xffffffffu, scan2, 1);
    if (lane == 0) T2 = 1.0f;
    float w4[4];
#pragma unroll
    for (int q = 0; q < 4; ++q) { w4[q] = al[q] * T2; T2 *= om2[q]; }

    float ir = 0.0f, ig = 0.0f, ib = 0.0f, ivd = 0.0f, ws = 0.0f;
#pragma unroll
    for (int q = 0; q < 4; ++q) {
        ir = fmaf(w4[q], rr[q], ir);
        ig = fmaf(w4[q], rg[q], ig);
        ib = fmaf(w4[q], rb[q], ib);
        ivd += w4[q] / exp10f(zlf[q]);
        ws  += w4[q];
    }
#pragma unroll
    for (int o = 16; o; o >>= 1) {
        ir  += __shfl_xor_sync(0xffffffffu, ir, o);
        ig  += __shfl_xor_sync(0xffffffffu, ig, o);
        ib  += __shfl_xor_sync(0xffffffffu, ib, o);
        ivd += __shfl_xor_sync(0xffffffffu, ivd, o);
        ws  += __shfl_xor_sync(0xffffffffu, ws, o);
    }

    // ---- stores ----
    *(float4*)(oW + (size_t)ray * NFINE + lane * 4) =
        make_float4(w4[0], w4[1], w4[2], w4[3]);
    *(float4*)(oZ + (size_t)ray * NFINE + lane * 4) =
        make_float4((zlf[0] + 1.0f) * 0.5f, (zlf[1] + 1.0f) * 0.5f,
                    (zlf[2] + 1.0f) * 0.5f, (zlf[3] + 1.0f) * 0.5f);

    if (lane == 0) {
        float oneMw = 1.0f - ws;
        oImg[ray * 3 + 0] = ir + oneMw * gbg[0];
        oImg[ray * 3 + 1] = ig + oneMw * gbg[1];
        oImg[ray * 3 + 2] = ib + oneMw * gbg[2];
        oInv[ray] = ivd;
    }
}

extern "C" void kernel_launch(void* const* d_in, const int* in_sizes, int n_in,
                              void* d_out, int out_size) {
    const float* h   = (const float*)d_in[1];
    const float* w   = (const float*)d_in[2];
    const float* K   = (const float*)d_in[3];
    const float* E   = (const float*)d_in[4];
    const float* bg  = (const float*)d_in[5];
    const float* Wd1 = (const float*)d_in[6];
    const float* bd1 = (const float*)d_in[7];
    const float* Wd2 = (const float*)d_in[8];
    const float* bd2 = (const float*)d_in[9];
    const float* Wc1 = (const float*)d_in[10];
    const float* bc1 = (const float*)d_in[11];
    const float* Wc2 = (const float*)d_in[12];
    const float* bc2 = (const float*)d_in[13];

    float* out   = (float*)d_out;
    float* oImg  = out;
    float* oW    = out + NRAYS * 3;
    float* oZ    = oW + (size_t)NRAYS * NFINE;
    float* oInv  = oZ + (size_t)NRAYS * NFINE;

    nerf_fused<<<NRAYS / 4, 128>>>(h, w, K, E, bg,
                                   Wd1, bd1, Wd2, bd2,
                                   Wc1, bc1, Wc2, bc2,
                                   oImg, oW, oZ, oInv);
}

// round 3
// speedup vs baseline: 2.0551x; 1.0284x over previous
#include <cuda_runtime.h>
#include <cstdint>

#define NRAYS 16384
#define NFINE 128

typedef unsigned long long u64;

// ---- packed fp32x2 helpers (sm_100+ PTX) ----
__device__ __forceinline__ u64 pack2(float lo, float hi) {
    u64 r; asm("mov.b64 %0, {%1, %2};" : "=l"(r) : "f"(lo), "f"(hi)); return r;
}
__device__ __forceinline__ void unpack2(u64 v, float& lo, float& hi) {
    asm("mov.b64 {%0, %1}, %2;" : "=f"(lo), "=f"(hi) : "l"(v));
}
__device__ __forceinline__ void fma2(u64& d, u64 a, u64 b) {
    asm("fma.rn.f32x2 %0, %1, %2, %0;" : "+l"(d) : "l"(a), "l"(b));
}

// exact z-grid helpers
__device__ __forceinline__ float zlog_c(int i) {
    return (i < 128) ? (float)(i - 128) * 0.0078125f : (float)(i - 128) * 0.015625f;
}
__device__ __forceinline__ float zmid_c(int i) {
    return 0.5f * (zlog_c(i) + zlog_c(i + 1));
}

__device__ __forceinline__ unsigned rotl32(unsigned x, int r) {
    return __funnelshift_l(x, x, r);
}

// JAX threefry2x32, key=(0,42), partitionable counter mode: bits = out0^out1
__device__ __forceinline__ float tf_uniform(unsigned idx) {
    unsigned x0 = 0u, x1 = idx;
    const unsigned ks1 = 42u;
    const unsigned ks2 = 42u ^ 0x1BD11BDAu;
    x0 += 0u; x1 += ks1;
#define TF_RND(R) { x0 += x1; x1 = rotl32(x1, R); x1 ^= x0; }
    TF_RND(13) TF_RND(15) TF_RND(26) TF_RND(6)
    x0 += ks1; x1 += ks2 + 1u;
    TF_RND(17) TF_RND(29) TF_RND(16) TF_RND(24)
    x0 += ks2; x1 += 0u + 2u;
    TF_RND(13) TF_RND(15) TF_RND(26) TF_RND(6)
    x0 += 0u; x1 += ks1 + 3u;
    TF_RND(17) TF_RND(29) TF_RND(16) TF_RND(24)
    x0 += ks1; x1 += ks2 + 4u;
    TF_RND(13) TF_RND(15) TF_RND(26) TF_RND(6)
    x0 += ks2; x1 += 0u + 5u;
#undef TF_RND
    unsigned bits = x0 ^ x1;
    return __uint_as_float((bits >> 9) | 0x3f800000u) - 1.0f;
}

__device__ __forceinline__ float softplus_f(float x) {
    return fmaxf(x, 0.0f) + log1pf(expf(-fabsf(x)));
}

__device__ __forceinline__ void mip_scale(float& x, float& y, float& z) {
    float d = sqrtf(x * x + y * y + z * z);
    if (d > 1.0f) {
        float s = (2.0f - 1.0f / d) / d;
        x *= s; y *= s; z *= s;
    }
}

__global__ void __launch_bounds__(128, 3) nerf_fused(
    const float* __restrict__ gh, const float* __restrict__ gw,
    const float* __restrict__ gK, const float* __restrict__ gE,
    const float* __restrict__ gbg,
    const float* __restrict__ gWd1, const float* __restrict__ gbd1,
    const float* __restrict__ gWd2, const float* __restrict__ gbd2,
    const float* __restrict__ gWc1, const float* __restrict__ gbc1,
    const float* __restrict__ gWc2, const float* __restrict__ gbc2,
    float* __restrict__ oImg, float* __restrict__ oW,
    float* __restrict__ oZ, float* __restrict__ oInv)
{
    __shared__ float4 sWd1p[32];                      // (w0,w1,w2,b) per hidden c
    __shared__ float  sWd2[32];
    __shared__ __align__(16) float sWc1[1120];        // [35][32] row-major
    __shared__ __align__(16) float sBc1[32];
    __shared__ __align__(16) float sWc2c[3][32];      // column-major Wc2
    __shared__ float sCdf[4][192];

    const int tid = threadIdx.x;
    for (int i = tid; i < 1120; i += 128) sWc1[i] = gWc1[i];
    if (tid < 32) {
        sWd1p[tid] = make_float4(gWd1[tid], gWd1[32 + tid], gWd1[64 + tid], gbd1[tid]);
        sWd2[tid]  = gWd2[tid];
        sBc1[tid]  = gbc1[tid];
        sWc2c[0][tid] = gWc2[tid * 3 + 0];
        sWc2c[1][tid] = gWc2[tid * 3 + 1];
        sWc2c[2][tid] = gWc2[tid * 3 + 2];
    }
    __syncthreads();

    const int lane = tid & 31;
    const int warp = tid >> 5;
    const int ray  = (blockIdx.x << 2) + warp;

    // ---- ray setup ----
    float k00 = gK[0], k01 = gK[1], k02 = gK[2];
    float k10 = gK[3], k11 = gK[4], k12 = gK[5];
    float k20 = gK[6], k21 = gK[7], k22 = gK[8];
    float det = k00 * (k11 * k22 - k12 * k21)
              + k01 * (k12 * k20 - k10 * k22)
              + k02 * (k10 * k21 - k11 * k20);
    float id = 1.0f / det;
    float i00 = (k11 * k22 - k12 * k21) * id, i01 = (k02 * k21 - k01 * k22) * id, i02 = (k01 * k12 - k02 * k11) * id;
    float i10 = (k12 * k20 - k10 * k22) * id, i11 = (k00 * k22 - k02 * k20) * id, i12 = (k02 * k10 - k00 * k12) * id;
    float i20 = (k10 * k21 - k11 * k20) * id, i21 = (k01 * k20 - k00 * k21) * id, i22 = (k00 * k11 - k01 * k10) * id;

    float dvx = gw[ray] + 0.5f, dvy = gh[ray] + 0.5f;
    float cx = dvx * i00 + dvy * i01 + i02;
    float cy = dvx * i10 + dvy * i11 + i12;
    float cz = dvx * i20 + dvy * i21 + i22;

    const float* Er = gE + (size_t)ray * 16;
    float ox = Er[3], oy = Er[7], oz = Er[11];
    float rdx = Er[0] * cx + Er[1] * cy + Er[2]  * cz;
    float rdy = Er[4] * cx + Er[5] * cy + Er[6]  * cz;
    float rdz = Er[8] * cx + Er[9] * cy + Er[10] * cz;
    float rn  = sqrtf(rdx * rdx + rdy * rdy + rdz * rdz);
    float ndx = rdx / rn, ndy = rdy / rn, ndz = rdz / rn;

    const float bd2v = gbd2[0];
    const float bc2x = gbc2[0], bc2y = gbc2[1], bc2z = gbc2[2];

    // ---- coarse pass: 6 samples/lane, density MLP only ----
    float alpha[6];
#pragma unroll
    for (int p = 0; p < 3; ++p) {
        const int s0 = lane * 6 + 2 * p;
        float zl0 = zlog_c(s0), zl1 = zlog_c(s0 + 1);
        float z0 = exp10f(zl0), z1 = exp10f(zl1);
        float px0 = fmaf(rdx, z0, ox), py0 = fmaf(rdy, z0, oy), pz0 = fmaf(rdz, z0, oz);
        float px1 = fmaf(rdx, z1, ox), py1 = fmaf(rdy, z1, oy), pz1 = fmaf(rdz, z1, oz);
        mip_scale(px0, py0, pz0);
        mip_scale(px1, py1, pz1);
        float sg0 = bd2v, sg1 = bd2v;
#pragma unroll 4
        for (int c = 0; c < 32; ++c) {
            float4 wd = sWd1p[c];
            float v2 = sWd2[c];
            float t0 = fmaf(px0, wd.x, fmaf(py0, wd.y, fmaf(pz0, wd.z, wd.w)));
            float t1 = fmaf(px1, wd.x, fmaf(py1, wd.y, fmaf(pz1, wd.z, wd.w)));
            t0 = fmaxf(t0, 0.0f); t1 = fmaxf(t1, 0.0f);
            sg0 = fmaf(t0, v2, sg0); sg1 = fmaf(t1, v2, sg1);
        }
        float si0 = softplus_f(sg0), si1 = softplus_f(sg1);
        float d0 = (s0     < 128) ? 0.0078125f : ((s0     < 191) ? 0.015625f : 0.0f);
        float d1 = (s0 + 1 < 128) ? 0.0078125f : ((s0 + 1 < 191) ? 0.015625f : 0.0f);
        alpha[2 * p]     = 1.0f - expf(-si0 * d0);
        alpha[2 * p + 1] = 1.0f - expf(-si1 * d1);
    }

    // ---- transmittance weights (warp multiplicative scan) ----
    float om[6]; float lprod = 1.0f;
#pragma unroll
    for (int q = 0; q < 6; ++q) { om[q] = 1.0f - alpha[q]; lprod *= om[q]; }
    float scanp = lprod;
#pragma unroll
    for (int o = 1; o < 32; o <<= 1) {
        float t = __shfl_up_sync(0xffffffffu, scanp, o);
        if (lane >= o) scanp *= t;
    }
    float T = __shfl_up_sync(0xffffffffu, scanp, 1);
    if (lane == 0) T = 1.0f;
    float wgt[6];
#pragma unroll
    for (int q = 0; q < 6; ++q) { wgt[q] = alpha[q] * T; T *= om[q]; }

    // ---- reweight ----
    float wprev = __shfl_up_sync(0xffffffffu, wgt[5], 1);   if (lane == 0)  wprev = 0.0f;
    float wnext = __shfl_down_sync(0xffffffffu, wgt[0], 1); if (lane == 31) wnext = 0.0f;
    float wr[6]; float lsum = 0.0f;
#pragma unroll
    for (int q = 0; q < 6; ++q) {
        float wm = (q == 0) ? wprev : wgt[q - 1];
        float wp = (q == 5) ? wnext : wgt[q + 1];
        float v = 0.5f * (fmaxf(wm, wgt[q]) + fmaxf(wgt[q], wp)) + (float)(0.02 / 192.0);
        int s = lane * 6 + q;
        v *= (s < 128) ? (float)(128.0 / 192.0) : (float)(64.0 / 192.0);
        wr[q] = v; lsum += v;
    }
    float tot = lsum;
#pragma unroll
    for (int o = 16; o; o >>= 1) tot += __shfl_xor_sync(0xffffffffu, tot, o);

    float wn[6]; float ls2 = 0.0f;
#pragma unroll
    for (int q = 0; q < 6; ++q) { wn[q] = wr[q] / tot; ls2 += wn[q]; }
    float scs = ls2;
#pragma unroll
    for (int o = 1; o < 32; o <<= 1) {
        float t = __shfl_up_sync(0xffffffffu, scs, o);
        if (lane >= o) scs += t;
    }
    float base = __shfl_up_sync(0xffffffffu, scs, 1);
    if (lane == 0) base = 0.0f;
    float run = base;
#pragma unroll
    for (int q = 0; q < 6; ++q) { run += wn[q]; sCdf[warp][lane * 6 + q] = run; }
    __syncwarp();

    const float cdfl = sCdf[warp][1];
    const float cdfh = sCdf[warp][190];

    // ---- importance sampling: branchless bit-ladder searchsorted ----
    float zlf[4];
#pragma unroll
    for (int q = 0; q < 4; ++q) {
        int j = (lane << 2) + q;
        float r = tf_uniform((unsigned)(ray * NFINE + j));
        float u = (float)j * 0.0078125f + r * 0.0078125f;
        u = u * (cdfh - cdfl) + cdfl;
        int k = 0;
#pragma unroll
        for (int s = 128; s >= 1; s >>= 1) {
            int cand = k + s;
            if (cand <= 189 && sCdf[warp][cand] <= u) k = cand;
        }
        float cb = sCdf[warp][k], ca = sCdf[warp][k + 1];
        float tt = (u - cb) / (ca - cb);
        float zb = zmid_c(k), za = zmid_c(k + 1);
        zlf[q] = zb + (za - zb) * tt;
    }

    // ---- fine pass: streamed features, packed f32x2 over j-pairs ----
    float sig[4], rr[4], rg[4], rb[4];
#pragma unroll
    for (int p = 0; p < 2; ++p) {
        const int q0 = 2 * p, q1 = 2 * p + 1;
        float z0 = exp10f(zlf[q0]), z1 = exp10f(zlf[q1]);
        float px0 = fmaf(rdx, z0, ox), py0 = fmaf(rdy, z0, oy), pz0 = fmaf(rdz, z0, oz);
        float px1 = fmaf(rdx, z1, ox), py1 = fmaf(rdy, z1, oy), pz1 = fmaf(rdz, z1, oz);
        mip_scale(px0, py0, pz0);
        mip_scale(px1, py1, pz1);

        // packed accumulators: acc0p[i] holds (acc[2i], acc[2i+1]) for sample q0
        u64 acc0p[16], acc1p[16];
        {
            u64 ndxp = pack2(ndx, ndx), ndyp = pack2(ndy, ndy), ndzp = pack2(ndz, ndz);
            const ulonglong2* b2  = (const ulonglong2*)sBc1;
            const ulonglong2* wx2 = (const ulonglong2*)&sWc1[1024];
            const ulonglong2* wy2 = (const ulonglong2*)&sWc1[1056];
            const ulonglong2* wz2 = (const ulonglong2*)&sWc1[1088];
#pragma unroll
            for (int g = 0; g < 8; ++g) {
                ulonglong2 b  = b2[g];
                ulonglong2 wx = wx2[g];
                ulonglong2 wy = wy2[g];
                ulonglong2 wz = wz2[g];
                u64 va = b.x, vb = b.y;
                fma2(va, ndxp, wx.x); fma2(vb, ndxp, wx.y);
                fma2(va, ndyp, wy.x); fma2(vb, ndyp, wy.y);
                fma2(va, ndzp, wz.x); fma2(vb, ndzp, wz.y);
                acc0p[2 * g] = va; acc1p[2 * g] = va;
                acc0p[2 * g + 1] = vb; acc1p[2 * g + 1] = vb;
            }
        }

        float sg0 = bd2v, sg1 = bd2v;
#pragma unroll 2
        for (int c = 0; c < 32; ++c) {
            float4 wd = sWd1p[c];
            float v2 = sWd2[c];
            float t0 = fmaf(px0, wd.x, fmaf(py0, wd.y, fmaf(pz0, wd.z, wd.w)));
            float t1 = fmaf(px1, wd.x, fmaf(py1, wd.y, fmaf(pz1, wd.z, wd.w)));
            t0 = fmaxf(t0, 0.0f); t1 = fmaxf(t1, 0.0f);
            sg0 = fmaf(t0, v2, sg0); sg1 = fmaf(t1, v2, sg1);
            u64 t00 = pack2(t0, t0);
            u64 t11 = pack2(t1, t1);
            const ulonglong2* wc = (const ulonglong2*)&sWc1[c * 32];
#pragma unroll
            for (int g = 0; g < 8; ++g) {
                ulonglong2 wv = wc[g];
                fma2(acc0p[2 * g],     t00, wv.x);
                fma2(acc0p[2 * g + 1], t00, wv.y);
                fma2(acc1p[2 * g],     t11, wv.x);
                fma2(acc1p[2 * g + 1], t11, wv.y);
            }
        }
        sig[q0] = softplus_f(sg0);
        sig[q1] = softplus_f(sg1);

        // color layer2 (scalar; unpack + relu + 3-color fma)
        float a0r = bc2x, a0g = bc2y, a0b = bc2z;
        float a1r = bc2x, a1g = bc2y, a1b = bc2z;
#pragma unroll
        for (int g = 0; g < 8; ++g) {
            int j4 = 4 * g;
            float4 u0 = *(const float4*)&sWc2c[0][j4];
            float4 u1 = *(const float4*)&sWc2c[1][j4];
            float4 u2 = *(const float4*)&sWc2c[2][j4];
            float h00, h01, h02, h03, h10, h11, h12, h13;
            unpack2(acc0p[2 * g],     h00, h01);
            unpack2(acc0p[2 * g + 1], h02, h03);
            unpack2(acc1p[2 * g],     h10, h11);
            unpack2(acc1p[2 * g + 1], h12, h13);
            h00 = fmaxf(h00, 0.0f); h01 = fmaxf(h01, 0.0f);
            h02 = fmaxf(h02, 0.0f); h03 = fmaxf(h03, 0.0f);
            h10 = fmaxf(h10, 0.0f); h11 = fmaxf(h11, 0.0f);
            h12 = fmaxf(h12, 0.0f); h13 = fmaxf(h13, 0.0f);
            a0r = fmaf(h00, u0.x, a0r); a0g = fmaf(h00, u1.x, a0g); a0b = fmaf(h00, u2.x, a0b);
            a1r = fmaf(h10, u0.x, a1r); a1g = fmaf(h10, u1.x, a1g); a1b = fmaf(h10, u2.x, a1b);
            a0r = fmaf(h01, u0.y, a0r); a0g = fmaf(h01, u1.y, a0g); a0b = fmaf(h01, u2.y, a0b);
            a1r = fmaf(h11, u0.y, a1r); a1g = fmaf(h11, u1.y, a1g); a1b = fmaf(h11, u2.y, a1b);
            a0r = fmaf(h02, u0.z, a0r); a0g = fmaf(h02, u1.z, a0g); a0b = fmaf(h02, u2.z, a0b);
            a1r = fmaf(h12, u0.z, a1r); a1g = fmaf(h12, u1.z, a1g); a1b = fmaf(h12, u2.z, a1b);
            a0r = fmaf(h03, u0.w, a0r); a0g = fmaf(h03, u1.w, a0g); a0b = fmaf(h03, u2.w, a0b);
            a1r = fmaf(h13, u0.w, a1r); a1g = fmaf(h13, u1.w, a1g); a1b = fmaf(h13, u2.w, a1b);
        }
        rr[q0] = 1.0f / (1.0f + expf(-a0r));
        rg[q0] = 1.0f / (1.0f + expf(-a0g));
        rb[q0] = 1.0f / (1.0f + expf(-a0b));
        rr[q1] = 1.0f / (1.0f + expf(-a1r));
        rg[q1] = 1.0f / (1.0f + expf(-a1g));
        rb[q1] = 1.0f / (1.0f + expf(-a1b));
    }

    // ---- fine weights + accumulation ----
    float znx = __shfl_down_sync(0xffffffffu, zlf[0], 1);
    float dl[4];
    dl[0] = zlf[1] - zlf[0];
    dl[1] = zlf[2] - zlf[1];
    dl[2] = zlf[3] - zlf[2];
    dl[3] = (lane == 31) ? 0.0f : (znx - zlf[3]);

    float al[4], om2[4]; float lp = 1.0f;
#pragma unroll
    for (int q = 0; q < 4; ++q) {
        al[q] = 1.0f - expf(-sig[q] * dl[q]);
        om2[q] = 1.0f - al[q];
        lp *= om2[q];
    }
    float scan2 = lp;
#pragma unroll
    for (int o = 1; o < 32; o <<= 1) {
        float t = __shfl_up_sync(0xffffffffu, scan2, o);
        if (lane >= o) scan2 *= t;
    }
    float T2 = __shfl_up_sync(0xffffffffu, scan2, 1);
    if (lane == 0) T2 = 1.0f;
    float w4[4];
#pragma unroll
    for (int q = 0; q < 4; ++q) { w4[q] = al[q] * T2; T2 *= om2[q]; }

    float ir = 0.0f, ig = 0.0f, ib = 0.0f, ivd = 0.0f, ws = 0.0f;
#pragma unroll
    for (int q = 0; q < 4; ++q) {
        ir = fmaf(w4[q], rr[q], ir);
        ig = fmaf(w4[q], rg[q], ig);
        ib = fmaf(w4[q], rb[q], ib);
        ivd += w4[q] / exp10f(zlf[q]);
        ws  += w4[q];
    }
#pragma unroll
    for (int o = 16; o; o >>= 1) {
        ir  += __shfl_xor_sync(0xffffffffu, ir, o);
        ig  += __shfl_xor_sync(0xffffffffu, ig, o);
        ib  += __shfl_xor_sync(0xffffffffu, ib, o);
        ivd += __shfl_xor_sync(0xffffffffu, ivd, o);
        ws  += __shfl_xor_sync(0xffffffffu, ws, o);
    }

    // ---- stores ----
    *(float4*)(oW + (size_t)ray * NFINE + lane * 4) =
        make_float4(w4[0], w4[1], w4[2], w4[3]);
    *(float4*)(oZ + (size_t)ray * NFINE + lane * 4) =
        make_float4((zlf[0] + 1.0f) * 0.5f, (zlf[1] + 1.0f) * 0.5f,
                    (zlf[2] + 1.0f) * 0.5f, (zlf[3] + 1.0f) * 0.5f);

    if (lane == 0) {
        float oneMw = 1.0f - ws;
        oImg[ray * 3 + 0] = ir + oneMw * gbg[0];
        oImg[ray * 3 + 1] = ig + oneMw * gbg[1];
        oImg[ray * 3 + 2] = ib + oneMw * gbg[2];
        oInv[ray] = ivd;
    }
}

extern "C" void kernel_launch(void* const* d_in, const int* in_sizes, int n_in,
                              void* d_out, int out_size) {
    const float* h   = (const float*)d_in[1];
    const float* w   = (const float*)d_in[2];
    const float* K   = (const float*)d_in[3];
    const float* E   = (const float*)d_in[4];
    const float* bg  = (const float*)d_in[5];
    const float* Wd1 = (const float*)d_in[6];
    const float* bd1 = (const float*)d_in[7];
    const float* Wd2 = (const float*)d_in[8];
    const float* bd2 = (const float*)d_in[9];
    const float* Wc1 = (const float*)d_in[10];
    const float* bc1 = (const float*)d_in[11];
    const float* Wc2 = (const float*)d_in[12];
    const float* bc2 = (const float*)d_in[13];

    float* out   = (float*)d_out;
    float* oImg  = out;
    float* oW    = out + NRAYS * 3;
    float* oZ    = oW + (size_t)NRAYS * NFINE;
    float* oInv  = oZ + (size_t)NRAYS * NFINE;

    nerf_fused<<<NRAYS / 4, 128>>>(h, w, K, E, bg,
                                   Wd1, bd1, Wd2, bd2,
                                   Wc1, bc1, Wc2, bc2,
                                   oImg, oW, oZ, oInv);
}

// round 4
// speedup vs baseline: 2.4415x; 1.1880x over previous
#include <cuda_runtime.h>
#include <cstdint>

#define NRAYS 16384
#define NFINE 128

typedef unsigned long long u64;

// ---- packed fp32x2 helpers (sm_100+ PTX) ----
__device__ __forceinline__ u64 pack2(float lo, float hi) {
    u64 r; asm("mov.b64 %0, {%1, %2};" : "=l"(r) : "f"(lo), "f"(hi)); return r;
}
__device__ __forceinline__ void unpack2(u64 v, float& lo, float& hi) {
    asm("mov.b64 {%0, %1}, %2;" : "=f"(lo), "=f"(hi) : "l"(v));
}
__device__ __forceinline__ void fma2(u64& d, u64 a, u64 b) {
    asm("fma.rn.f32x2 %0, %1, %2, %0;" : "+l"(d) : "l"(a), "l"(b));
}

// ---- fast transcendentals (MUFU-based; rel err ~2^-21 << 1e-3 tol) ----
__device__ __forceinline__ float fexp(float x)   { return __expf(x); }
__device__ __forceinline__ float fexp10(float x) { return __exp10f(x); }
__device__ __forceinline__ float fsigmoid(float x) {
    return __fdividef(1.0f, 1.0f + __expf(-x));
}
__device__ __forceinline__ float fsoftplus(float x) {
    return fmaxf(x, 0.0f) + __logf(1.0f + __expf(-fabsf(x)));
}

// exact z-grid helpers
__device__ __forceinline__ float zlog_c(int i) {
    return (i < 128) ? (float)(i - 128) * 0.0078125f : (float)(i - 128) * 0.015625f;
}
__device__ __forceinline__ float zmid_c(int i) {
    return 0.5f * (zlog_c(i) + zlog_c(i + 1));
}

__device__ __forceinline__ unsigned rotl32(unsigned x, int r) {
    return __funnelshift_l(x, x, r);
}

// JAX threefry2x32, key=(0,42), partitionable counter mode: bits = out0^out1
__device__ __forceinline__ float tf_uniform(unsigned idx) {
    unsigned x0 = 0u, x1 = idx;
    const unsigned ks1 = 42u;
    const unsigned ks2 = 42u ^ 0x1BD11BDAu;
    x0 += 0u; x1 += ks1;
#define TF_RND(R) { x0 += x1; x1 = rotl32(x1, R); x1 ^= x0; }
    TF_RND(13) TF_RND(15) TF_RND(26) TF_RND(6)
    x0 += ks1; x1 += ks2 + 1u;
    TF_RND(17) TF_RND(29) TF_RND(16) TF_RND(24)
    x0 += ks2; x1 += 0u + 2u;
    TF_RND(13) TF_RND(15) TF_RND(26) TF_RND(6)
    x0 += 0u; x1 += ks1 + 3u;
    TF_RND(17) TF_RND(29) TF_RND(16) TF_RND(24)
    x0 += ks1; x1 += ks2 + 4u;
    TF_RND(13) TF_RND(15) TF_RND(26) TF_RND(6)
    x0 += ks2; x1 += 0u + 5u;
#undef TF_RND
    unsigned bits = x0 ^ x1;
    return __uint_as_float((bits >> 9) | 0x3f800000u) - 1.0f;
}

__device__ __forceinline__ void mip_scale(float& x, float& y, float& z) {
    float d = sqrtf(x * x + y * y + z * z);
    if (d > 1.0f) {
        float s = (2.0f - __frcp_rn(d)) * __frcp_rn(d);
        // keep precise: recompute with exact divides to stay near reference
        s = (2.0f - 1.0f / d) / d;
        x *= s; y *= s; z *= s;
    }
}

__global__ void __launch_bounds__(128, 4) nerf_fused(
    const float* __restrict__ gh, const float* __restrict__ gw,
    const float* __restrict__ gK, const float* __restrict__ gE,
    const float* __restrict__ gbg,
    const float* __restrict__ gWd1, const float* __restrict__ gbd1,
    const float* __restrict__ gWd2, const float* __restrict__ gbd2,
    const float* __restrict__ gWc1, const float* __restrict__ gbc1,
    const float* __restrict__ gWc2, const float* __restrict__ gbc2,
    float* __restrict__ oImg, float* __restrict__ oW,
    float* __restrict__ oZ, float* __restrict__ oInv)
{
    __shared__ float4 sWd1p[32];                      // (w0,w1,w2,b) per hidden c
    __shared__ float  sWd2[32];
    __shared__ __align__(16) float sWc1[1120];        // [35][32] row-major
    __shared__ __align__(16) float sBc1[32];
    __shared__ __align__(16) float sWc2c[3][32];      // column-major Wc2
    __shared__ float sCdf[4][192];

    const int tid = threadIdx.x;
    for (int i = tid; i < 1120; i += 128) sWc1[i] = gWc1[i];
    if (tid < 32) {
        sWd1p[tid] = make_float4(gWd1[tid], gWd1[32 + tid], gWd1[64 + tid], gbd1[tid]);
        sWd2[tid]  = gWd2[tid];
        sBc1[tid]  = gbc1[tid];
        sWc2c[0][tid] = gWc2[tid * 3 + 0];
        sWc2c[1][tid] = gWc2[tid * 3 + 1];
        sWc2c[2][tid] = gWc2[tid * 3 + 2];
    }
    __syncthreads();

    const int lane = tid & 31;
    const int warp = tid >> 5;
    const int ray  = (blockIdx.x << 2) + warp;

    // ---- ray setup ----
    float k00 = gK[0], k01 = gK[1], k02 = gK[2];
    float k10 = gK[3], k11 = gK[4], k12 = gK[5];
    float k20 = gK[6], k21 = gK[7], k22 = gK[8];
    float det = k00 * (k11 * k22 - k12 * k21)
              + k01 * (k12 * k20 - k10 * k22)
              + k02 * (k10 * k21 - k11 * k20);
    float id = 1.0f / det;
    float i00 = (k11 * k22 - k12 * k21) * id, i01 = (k02 * k21 - k01 * k22) * id, i02 = (k01 * k12 - k02 * k11) * id;
    float i10 = (k12 * k20 - k10 * k22) * id, i11 = (k00 * k22 - k02 * k20) * id, i12 = (k02 * k10 - k00 * k12) * id;
    float i20 = (k10 * k21 - k11 * k20) * id, i21 = (k01 * k20 - k00 * k21) * id, i22 = (k00 * k11 - k01 * k10) * id;

    float dvx = gw[ray] + 0.5f, dvy = gh[ray] + 0.5f;
    float cx = dvx * i00 + dvy * i01 + i02;
    float cy = dvx * i10 + dvy * i11 + i12;
    float cz = dvx * i20 + dvy * i21 + i22;

    const float* Er = gE + (size_t)ray * 16;
    float ox = Er[3], oy = Er[7], oz = Er[11];
    float rdx = Er[0] * cx + Er[1] * cy + Er[2]  * cz;
    float rdy = Er[4] * cx + Er[5] * cy + Er[6]  * cz;
    float rdz = Er[8] * cx + Er[9] * cy + Er[10] * cz;
    float rn  = sqrtf(rdx * rdx + rdy * rdy + rdz * rdz);
    float ndx = rdx / rn, ndy = rdy / rn, ndz = rdz / rn;

    const float bd2v = gbd2[0];

    // ---- coarse pass: 6 samples/lane, density MLP only ----
    float alpha[6];
#pragma unroll
    for (int p = 0; p < 3; ++p) {
        const int s0 = lane * 6 + 2 * p;
        float zl0 = zlog_c(s0), zl1 = zlog_c(s0 + 1);
        float z0 = fexp10(zl0), z1 = fexp10(zl1);
        float px0 = fmaf(rdx, z0, ox), py0 = fmaf(rdy, z0, oy), pz0 = fmaf(rdz, z0, oz);
        float px1 = fmaf(rdx, z1, ox), py1 = fmaf(rdy, z1, oy), pz1 = fmaf(rdz, z1, oz);
        mip_scale(px0, py0, pz0);
        mip_scale(px1, py1, pz1);
        float sg0 = bd2v, sg1 = bd2v;
#pragma unroll 4
        for (int c = 0; c < 32; ++c) {
            float4 wd = sWd1p[c];
            float v2 = sWd2[c];
            float t0 = fmaf(px0, wd.x, fmaf(py0, wd.y, fmaf(pz0, wd.z, wd.w)));
            float t1 = fmaf(px1, wd.x, fmaf(py1, wd.y, fmaf(pz1, wd.z, wd.w)));
            t0 = fmaxf(t0, 0.0f); t1 = fmaxf(t1, 0.0f);
            sg0 = fmaf(t0, v2, sg0); sg1 = fmaf(t1, v2, sg1);
        }
        float si0 = fsoftplus(sg0), si1 = fsoftplus(sg1);
        float d0 = (s0     < 128) ? 0.0078125f : ((s0     < 191) ? 0.015625f : 0.0f);
        float d1 = (s0 + 1 < 128) ? 0.0078125f : ((s0 + 1 < 191) ? 0.015625f : 0.0f);
        alpha[2 * p]     = 1.0f - fexp(-si0 * d0);
        alpha[2 * p + 1] = 1.0f - fexp(-si1 * d1);
    }

    // ---- transmittance weights (warp multiplicative scan) ----
    float om[6]; float lprod = 1.0f;
#pragma unroll
    for (int q = 0; q < 6; ++q) { om[q] = 1.0f - alpha[q]; lprod *= om[q]; }
    float scanp = lprod;
#pragma unroll
    for (int o = 1; o < 32; o <<= 1) {
        float t = __shfl_up_sync(0xffffffffu, scanp, o);
        if (lane >= o) scanp *= t;
    }
    float T = __shfl_up_sync(0xffffffffu, scanp, 1);
    if (lane == 0) T = 1.0f;
    float wgt[6];
#pragma unroll
    for (int q = 0; q < 6; ++q) { wgt[q] = alpha[q] * T; T *= om[q]; }

    // ---- reweight ----
    float wprev = __shfl_up_sync(0xffffffffu, wgt[5], 1);   if (lane == 0)  wprev = 0.0f;
    float wnext = __shfl_down_sync(0xffffffffu, wgt[0], 1); if (lane == 31) wnext = 0.0f;
    float wr[6]; float lsum = 0.0f;
#pragma unroll
    for (int q = 0; q < 6; ++q) {
        float wm = (q == 0) ? wprev : wgt[q - 1];
        float wp = (q == 5) ? wnext : wgt[q + 1];
        float v = 0.5f * (fmaxf(wm, wgt[q]) + fmaxf(wgt[q], wp)) + (float)(0.02 / 192.0);
        int s = lane * 6 + q;
        v *= (s < 128) ? (float)(128.0 / 192.0) : (float)(64.0 / 192.0);
        wr[q] = v; lsum += v;
    }
    float tot = lsum;
#pragma unroll
    for (int o = 16; o; o >>= 1) tot += __shfl_xor_sync(0xffffffffu, tot, o);

    float wn[6]; float ls2 = 0.0f;
#pragma unroll
    for (int q = 0; q < 6; ++q) { wn[q] = wr[q] / tot; ls2 += wn[q]; }
    float scs = ls2;
#pragma unroll
    for (int o = 1; o < 32; o <<= 1) {
        float t = __shfl_up_sync(0xffffffffu, scs, o);
        if (lane >= o) scs += t;
    }
    float base = __shfl_up_sync(0xffffffffu, scs, 1);
    if (lane == 0) base = 0.0f;
    float run = base;
#pragma unroll
    for (int q = 0; q < 6; ++q) { run += wn[q]; sCdf[warp][lane * 6 + q] = run; }
    __syncwarp();

    const float cdfl = sCdf[warp][1];
    const float cdfh = sCdf[warp][190];

    // ---- importance sampling: branchless bit-ladder searchsorted ----
    float zlf[4];
#pragma unroll
    for (int q = 0; q < 4; ++q) {
        int j = (lane << 2) + q;
        float r = tf_uniform((unsigned)(ray * NFINE + j));
        float u = (float)j * 0.0078125f + r * 0.0078125f;
        u = u * (cdfh - cdfl) + cdfl;
        int k = 0;
#pragma unroll
        for (int s = 128; s >= 1; s >>= 1) {
            int cand = k + s;
            if (cand <= 189 && sCdf[warp][cand] <= u) k = cand;
        }
        float cb = sCdf[warp][k], ca = sCdf[warp][k + 1];
        float tt = (u - cb) / (ca - cb);
        float zb = zmid_c(k), za = zmid_c(k + 1);
        zlf[q] = zb + (za - zb) * tt;
    }

    // ---- fine pass: streamed features, f32x2 over j-pairs, split in 2 j-halves ----
    float sig[4], rr[4], rg[4], rb[4];
#pragma unroll
    for (int p = 0; p < 2; ++p) {
        const int q0 = 2 * p, q1 = 2 * p + 1;
        float z0 = fexp10(zlf[q0]), z1 = fexp10(zlf[q1]);
        float px0 = fmaf(rdx, z0, ox), py0 = fmaf(rdy, z0, oy), pz0 = fmaf(rdz, z0, oz);
        float px1 = fmaf(rdx, z1, ox), py1 = fmaf(rdy, z1, oy), pz1 = fmaf(rdz, z1, oz);
        mip_scale(px0, py0, pz0);
        mip_scale(px1, py1, pz1);

        float a0r = gbc2[0], a0g = gbc2[1], a0b = gbc2[2];
        float a1r = a0r, a1g = a0g, a1b = a0b;
        float sg0 = bd2v, sg1 = bd2v;

#pragma unroll
        for (int hh = 0; hh < 2; ++hh) {
            const int jb = hh << 4;                       // j base: 0 or 16
            u64 acc0p[8], acc1p[8];
            {
                u64 ndxp = pack2(ndx, ndx), ndyp = pack2(ndy, ndy), ndzp = pack2(ndz, ndz);
                const ulonglong2* b2  = (const ulonglong2*)&sBc1[jb];
                const ulonglong2* wx2 = (const ulonglong2*)&sWc1[1024 + jb];
                const ulonglong2* wy2 = (const ulonglong2*)&sWc1[1056 + jb];
                const ulonglong2* wz2 = (const ulonglong2*)&sWc1[1088 + jb];
#pragma unroll
                for (int g = 0; g < 4; ++g) {
                    ulonglong2 b  = b2[g];
                    ulonglong2 wx = wx2[g];
                    ulonglong2 wy = wy2[g];
                    ulonglong2 wz = wz2[g];
                    u64 va = b.x, vb = b.y;
                    fma2(va, ndxp, wx.x); fma2(vb, ndxp, wx.y);
                    fma2(va, ndyp, wy.x); fma2(vb, ndyp, wy.y);
                    fma2(va, ndzp, wz.x); fma2(vb, ndzp, wz.y);
                    acc0p[2 * g] = va; acc1p[2 * g] = va;
                    acc0p[2 * g + 1] = vb; acc1p[2 * g + 1] = vb;
                }
            }

#pragma unroll 4
            for (int c = 0; c < 32; ++c) {
                float4 wd = sWd1p[c];
                float t0 = fmaf(px0, wd.x, fmaf(py0, wd.y, fmaf(pz0, wd.z, wd.w)));
                float t1 = fmaf(px1, wd.x, fmaf(py1, wd.y, fmaf(pz1, wd.z, wd.w)));
                t0 = fmaxf(t0, 0.0f); t1 = fmaxf(t1, 0.0f);
                if (hh == 0) {
                    float v2 = sWd2[c];
                    sg0 = fmaf(t0, v2, sg0); sg1 = fmaf(t1, v2, sg1);
                }
                u64 t00 = pack2(t0, t0);
                u64 t11 = pack2(t1, t1);
                const ulonglong2* wc = (const ulonglong2*)&sWc1[c * 32 + jb];
#pragma unroll
                for (int g = 0; g < 4; ++g) {
                    ulonglong2 wv = wc[g];
                    fma2(acc0p[2 * g],     t00, wv.x);
                    fma2(acc0p[2 * g + 1], t00, wv.y);
                    fma2(acc1p[2 * g],     t11, wv.x);
                    fma2(acc1p[2 * g + 1], t11, wv.y);
                }
            }

            // layer2 partial for this half
#pragma unroll
            for (int g = 0; g < 4; ++g) {
                int j4 = jb + 4 * g;
                float4 u0 = *(const float4*)&sWc2c[0][j4];
                float4 u1 = *(const float4*)&sWc2c[1][j4];
                float4 u2 = *(const float4*)&sWc2c[2][j4];
                float h00, h01, h02, h03, h10, h11, h12, h13;
                unpack2(acc0p[2 * g],     h00, h01);
                unpack2(acc0p[2 * g + 1], h02, h03);
                unpack2(acc1p[2 * g],     h10, h11);
                unpack2(acc1p[2 * g + 1], h12, h13);
                h00 = fmaxf(h00, 0.0f); h01 = fmaxf(h01, 0.0f);
                h02 = fmaxf(h02, 0.0f); h03 = fmaxf(h03, 0.0f);
                h10 = fmaxf(h10, 0.0f); h11 = fmaxf(h11, 0.0f);
                h12 = fmaxf(h12, 0.0f); h13 = fmaxf(h13, 0.0f);
                a0r = fmaf(h00, u0.x, a0r); a0g = fmaf(h00, u1.x, a0g); a0b = fmaf(h00, u2.x, a0b);
                a1r = fmaf(h10, u0.x, a1r); a1g = fmaf(h10, u1.x, a1g); a1b = fmaf(h10, u2.x, a1b);
                a0r = fmaf(h01, u0.y, a0r); a0g = fmaf(h01, u1.y, a0g); a0b = fmaf(h01, u2.y, a0b);
                a1r = fmaf(h11, u0.y, a1r); a1g = fmaf(h11, u1.y, a1g); a1b = fmaf(h11, u2.y, a1b);
                a0r = fmaf(h02, u0.z, a0r); a0g = fmaf(h02, u1.z, a0g); a0b = fmaf(h02, u2.z, a0b);
                a1r = fmaf(h12, u0.z, a1r); a1g = fmaf(h12, u1.z, a1g); a1b = fmaf(h12, u2.z, a1b);
                a0r = fmaf(h03, u0.w, a0r); a0g = fmaf(h03, u1.w, a0g); a0b = fmaf(h03, u2.w, a0b);
                a1r = fmaf(h13, u0.w, a1r); a1g = fmaf(h13, u1.w, a1g); a1b = fmaf(h13, u2.w, a1b);
            }
        }

        sig[q0] = fsoftplus(sg0);
        sig[q1] = fsoftplus(sg1);
        rr[q0] = fsigmoid(a0r); rg[q0] = fsigmoid(a0g); rb[q0] = fsigmoid(a0b);
        rr[q1] = fsigmoid(a1r); rg[q1] = fsigmoid(a1g); rb[q1] = fsigmoid(a1b);
    }

    // ---- fine weights + accumulation ----
    float znx = __shfl_down_sync(0xffffffffu, zlf[0], 1);
    float dl[4];
    dl[0] = zlf[1] - zlf[0];
    dl[1] = zlf[2] - zlf[1];
    dl[2] = zlf[3] - zlf[2];
    dl[3] = (lane == 31) ? 0.0f : (znx - zlf[3]);

    float al[4], om2[4]; float lp = 1.0f;
#pragma unroll
    for (int q = 0; q < 4; ++q) {
        al[q] = 1.0f - fexp(-sig[q] * dl[q]);
        om2[q] = 1.0f - al[q];
        lp *= om2[q];
    }
    float scan2 = lp;
#pragma unroll
    for (int o = 1; o < 32; o <<= 1) {
        float t = __shfl_up_sync(0xffffffffu, scan2, o);
        if (lane >= o) scan2 *= t;
    }
    float T2 = __shfl_up_sync(0xffffffffu, scan2, 1);
    if (lane == 0) T2 = 1.0f;
    float w4[4];
#pragma unroll
    for (int q = 0; q < 4; ++q) { w4[q] = al[q] * T2; T2 *= om2[q]; }

    float ir = 0.0f, ig = 0.0f, ib = 0.0f, ivd = 0.0f, ws = 0.0f;
#pragma unroll
    for (int q = 0; q < 4; ++q) {
        ir = fmaf(w4[q], rr[q], ir);
        ig = fmaf(w4[q], rg[q], ig);
        ib = fmaf(w4[q], rb[q], ib);
        ivd = fmaf(w4[q], fexp10(-zlf[q]), ivd);
        ws  += w4[q];
    }
#pragma unroll
    for (int o = 16; o; o >>= 1) {
        ir  += __shfl_xor_sync(0xffffffffu, ir, o);
        ig  += __shfl_xor_sync(0xffffffffu, ig, o);
        ib  += __shfl_xor_sync(0xffffffffu, ib, o);
        ivd += __shfl_xor_sync(0xffffffffu, ivd, o);
        ws  += __shfl_xor_sync(0xffffffffu, ws, o);
    }

    // ---- stores ----
    *(float4*)(oW + (size_t)ray * NFINE + lane * 4) =
        make_float4(w4[0], w4[1], w4[2], w4[3]);
    *(float4*)(oZ + (size_t)ray * NFINE + lane * 4) =
        make_float4((zlf[0] + 1.0f) * 0.5f, (zlf[1] + 1.0f) * 0.5f,
                    (zlf[2] + 1.0f) * 0.5f, (zlf[3] + 1.0f) * 0.5f);

    if (lane == 0) {
        float oneMw = 1.0f - ws;
        oImg[ray * 3 + 0] = ir + oneMw * gbg[0];
        oImg[ray * 3 + 1] = ig + oneMw * gbg[1];
        oImg[ray * 3 + 2] = ib + oneMw * gbg[2];
        oInv[ray] = ivd;
    }
}

extern "C" void kernel_launch(void* const* d_in, const int* in_sizes, int n_in,
                              void* d_out, int out_size) {
    const float* h   = (const float*)d_in[1];
    const float* w   = (const float*)d_in[2];
    const float* K   = (const float*)d_in[3];
    const float* E   = (const float*)d_in[4];
    const float* bg  = (const float*)d_in[5];
    const float* Wd1 = (const float*)d_in[6];
    const float* bd1 = (const float*)d_in[7];
    const float* Wd2 = (const float*)d_in[8];
    const float* bd2 = (const float*)d_in[9];
    const float* Wc1 = (const float*)d_in[10];
    const float* bc1 = (const float*)d_in[11];
    const float* Wc2 = (const float*)d_in[12];
    const float* bc2 = (const float*)d_in[13];

    float* out   = (float*)d_out;
    float* oImg  = out;
    float* oW    = out + NRAYS * 3;
    float* oZ    = oW + (size_t)NRAYS * NFINE;
    float* oInv  = oZ + (size_t)NRAYS * NFINE;

    nerf_fused<<<NRAYS / 4, 128>>>(h, w, K, E, bg,
                                   Wd1, bd1, Wd2, bd2,
                                   Wc1, bc1, Wc2, bc2,
                                   oImg, oW, oZ, oInv);
}

// round 5
// speedup vs baseline: 2.5851x; 1.0588x over previous
#include <cuda_runtime.h>
#include <cstdint>

#define NRAYS 16384
#define NFINE 128

typedef unsigned long long u64;

// ---- packed fp32x2 helpers (sm_100+ PTX) ----
__device__ __forceinline__ u64 pack2(float lo, float hi) {
    u64 r; asm("mov.b64 %0, {%1, %2};" : "=l"(r) : "f"(lo), "f"(hi)); return r;
}
__device__ __forceinline__ void unpack2(u64 v, float& lo, float& hi) {
    asm("mov.b64 {%0, %1}, %2;" : "=f"(lo), "=f"(hi) : "l"(v));
}
__device__ __forceinline__ void fma2(u64& d, u64 a, u64 b) {
    asm("fma.rn.f32x2 %0, %1, %2, %0;" : "+l"(d) : "l"(a), "l"(b));
}

// ---- fast transcendentals (MUFU-based; rel err ~2^-21 << 1e-3 tol) ----
__device__ __forceinline__ float fexp(float x)   { return __expf(x); }
__device__ __forceinline__ float fexp10(float x) { return __exp10f(x); }
__device__ __forceinline__ float frsqrt_approx(float x) {
    float r; asm("rsqrt.approx.f32 %0, %1;" : "=f"(r) : "f"(x)); return r;
}
__device__ __forceinline__ float fsigmoid(float x) {
    return __fdividef(1.0f, 1.0f + __expf(-x));
}
__device__ __forceinline__ float fsoftplus(float x) {
    return fmaxf(x, 0.0f) + __logf(1.0f + __expf(-fabsf(x)));
}

// exact z-grid helpers
__device__ __forceinline__ float zlog_c(int i) {
    return (i < 128) ? (float)(i - 128) * 0.0078125f : (float)(i - 128) * 0.015625f;
}
__device__ __forceinline__ float zmid_c(int i) {
    return 0.5f * (zlog_c(i) + zlog_c(i + 1));
}

__device__ __forceinline__ unsigned rotl32(unsigned x, int r) {
    return __funnelshift_l(x, x, r);
}

// JAX threefry2x32, key=(0,42), partitionable counter mode: bits = out0^out1
__device__ __forceinline__ float tf_uniform(unsigned idx) {
    unsigned x0 = 0u, x1 = idx;
    const unsigned ks1 = 42u;
    const unsigned ks2 = 42u ^ 0x1BD11BDAu;
    x0 += 0u; x1 += ks1;
#define TF_RND(R) { x0 += x1; x1 = rotl32(x1, R); x1 ^= x0; }
    TF_RND(13) TF_RND(15) TF_RND(26) TF_RND(6)
    x0 += ks1; x1 += ks2 + 1u;
    TF_RND(17) TF_RND(29) TF_RND(16) TF_RND(24)
    x0 += ks2; x1 += 0u + 2u;
    TF_RND(13) TF_RND(15) TF_RND(26) TF_RND(6)
    x0 += 0u; x1 += ks1 + 3u;
    TF_RND(17) TF_RND(29) TF_RND(16) TF_RND(24)
    x0 += ks1; x1 += ks2 + 4u;
    TF_RND(13) TF_RND(15) TF_RND(26) TF_RND(6)
    x0 += ks2; x1 += 0u + 5u;
#undef TF_RND
    unsigned bits = x0 ^ x1;
    return __uint_as_float((bits >> 9) | 0x3f800000u) - 1.0f;
}

// mip scale via rsqrt trick: r = rsqrt(d2) == 1/d;  d = d2*r;  s = (2-r)*r
__device__ __forceinline__ void mip_scale(float& x, float& y, float& z) {
    float d2 = x * x + y * y + z * z;
    float r  = frsqrt_approx(d2);
    float d  = d2 * r;
    if (d > 1.0f) {
        float s = (2.0f - r) * r;
        x *= s; y *= s; z *= s;
    }
}

__global__ void __launch_bounds__(128, 4) nerf_fused(
    const float* __restrict__ gh, const float* __restrict__ gw,
    const float* __restrict__ gK, const float* __restrict__ gE,
    const float* __restrict__ gbg,
    const float* __restrict__ gWd1, const float* __restrict__ gbd1,
    const float* __restrict__ gWd2, const float* __restrict__ gbd2,
    const float* __restrict__ gWc1, const float* __restrict__ gbc1,
    const float* __restrict__ gWc2, const float* __restrict__ gbc2,
    float* __restrict__ oImg, float* __restrict__ oW,
    float* __restrict__ oZ, float* __restrict__ oInv)
{
    __shared__ float4 sWd1p[32];                      // (w0,w1,w2,b) per hidden c
    __shared__ float  sWd2[32];
    __shared__ __align__(16) float sWc1[1120];        // [35][32] row-major
    __shared__ __align__(16) float sBc1[32];
    __shared__ __align__(16) float sWc2c[3][32];      // column-major Wc2
    __shared__ float sCdf[4][256];                    // cdf + +inf padding for ladder

    const int tid = threadIdx.x;
    for (int i = tid; i < 1120; i += 128) sWc1[i] = gWc1[i];
    if (tid < 32) {
        sWd1p[tid] = make_float4(gWd1[tid], gWd1[32 + tid], gWd1[64 + tid], gbd1[tid]);
        sWd2[tid]  = gWd2[tid];
        sBc1[tid]  = gbc1[tid];
        sWc2c[0][tid] = gWc2[tid * 3 + 0];
        sWc2c[1][tid] = gWc2[tid * 3 + 1];
        sWc2c[2][tid] = gWc2[tid * 3 + 2];
    }
    __syncthreads();

    const int lane = tid & 31;
    const int warp = tid >> 5;
    const int ray  = (blockIdx.x << 2) + warp;

    // ---- ray setup ----
    float k00 = gK[0], k01 = gK[1], k02 = gK[2];
    float k10 = gK[3], k11 = gK[4], k12 = gK[5];
    float k20 = gK[6], k21 = gK[7], k22 = gK[8];
    float det = k00 * (k11 * k22 - k12 * k21)
              + k01 * (k12 * k20 - k10 * k22)
              + k02 * (k10 * k21 - k11 * k20);
    float id = 1.0f / det;
    float i00 = (k11 * k22 - k12 * k21) * id, i01 = (k02 * k21 - k01 * k22) * id, i02 = (k01 * k12 - k02 * k11) * id;
    float i10 = (k12 * k20 - k10 * k22) * id, i11 = (k00 * k22 - k02 * k20) * id, i12 = (k02 * k10 - k00 * k12) * id;
    float i20 = (k10 * k21 - k11 * k20) * id, i21 = (k01 * k20 - k00 * k21) * id, i22 = (k00 * k11 - k01 * k10) * id;

    float dvx = gw[ray] + 0.5f, dvy = gh[ray] + 0.5f;
    float cx = dvx * i00 + dvy * i01 + i02;
    float cy = dvx * i10 + dvy * i11 + i12;
    float cz = dvx * i20 + dvy * i21 + i22;

    const float* Er = gE + (size_t)ray * 16;
    float ox = Er[3], oy = Er[7], oz = Er[11];
    float rdx = Er[0] * cx + Er[1] * cy + Er[2]  * cz;
    float rdy = Er[4] * cx + Er[5] * cy + Er[6]  * cz;
    float rdz = Er[8] * cx + Er[9] * cy + Er[10] * cz;
    float rn  = sqrtf(rdx * rdx + rdy * rdy + rdz * rdz);
    float irn = __fdividef(1.0f, rn);
    float ndx = rdx * irn, ndy = rdy * irn, ndz = rdz * irn;

    const float bd2v = gbd2[0];

    // ---- coarse pass: 6 samples/lane, density MLP only ----
    float alpha[6];
#pragma unroll
    for (int p = 0; p < 3; ++p) {
        const int s0 = lane * 6 + 2 * p;
        float zl0 = zlog_c(s0), zl1 = zlog_c(s0 + 1);
        float z0 = fexp10(zl0), z1 = fexp10(zl1);
        float px0 = fmaf(rdx, z0, ox), py0 = fmaf(rdy, z0, oy), pz0 = fmaf(rdz, z0, oz);
        float px1 = fmaf(rdx, z1, ox), py1 = fmaf(rdy, z1, oy), pz1 = fmaf(rdz, z1, oz);
        mip_scale(px0, py0, pz0);
        mip_scale(px1, py1, pz1);
        float sg0 = bd2v, sg1 = bd2v;
#pragma unroll 4
        for (int c = 0; c < 32; ++c) {
            float4 wd = sWd1p[c];
            float v2 = sWd2[c];
            float t0 = fmaf(px0, wd.x, fmaf(py0, wd.y, fmaf(pz0, wd.z, wd.w)));
            float t1 = fmaf(px1, wd.x, fmaf(py1, wd.y, fmaf(pz1, wd.z, wd.w)));
            t0 = fmaxf(t0, 0.0f); t1 = fmaxf(t1, 0.0f);
            sg0 = fmaf(t0, v2, sg0); sg1 = fmaf(t1, v2, sg1);
        }
        float si0 = fsoftplus(sg0), si1 = fsoftplus(sg1);
        float d0 = (s0     < 128) ? 0.0078125f : ((s0     < 191) ? 0.015625f : 0.0f);
        float d1 = (s0 + 1 < 128) ? 0.0078125f : ((s0 + 1 < 191) ? 0.015625f : 0.0f);
        alpha[2 * p]     = 1.0f - fexp(-si0 * d0);
        alpha[2 * p + 1] = 1.0f - fexp(-si1 * d1);
    }

    // ---- transmittance weights (warp multiplicative scan) ----
    float om[6]; float lprod = 1.0f;
#pragma unroll
    for (int q = 0; q < 6; ++q) { om[q] = 1.0f - alpha[q]; lprod *= om[q]; }
    float scanp = lprod;
#pragma unroll
    for (int o = 1; o < 32; o <<= 1) {
        float t = __shfl_up_sync(0xffffffffu, scanp, o);
        if (lane >= o) scanp *= t;
    }
    float T = __shfl_up_sync(0xffffffffu, scanp, 1);
    if (lane == 0) T = 1.0f;
    float wgt[6];
#pragma unroll
    for (int q = 0; q < 6; ++q) { wgt[q] = alpha[q] * T; T *= om[q]; }

    // ---- reweight ----
    float wprev = __shfl_up_sync(0xffffffffu, wgt[5], 1);   if (lane == 0)  wprev = 0.0f;
    float wnext = __shfl_down_sync(0xffffffffu, wgt[0], 1); if (lane == 31) wnext = 0.0f;
    float wr[6]; float lsum = 0.0f;
#pragma unroll
    for (int q = 0; q < 6; ++q) {
        float wm = (q == 0) ? wprev : wgt[q - 1];
        float wp = (q == 5) ? wnext : wgt[q + 1];
        float v = 0.5f * (fmaxf(wm, wgt[q]) + fmaxf(wgt[q], wp)) + (float)(0.02 / 192.0);
        int s = lane * 6 + q;
        v *= (s < 128) ? (float)(128.0 / 192.0) : (float)(64.0 / 192.0);
        wr[q] = v; lsum += v;
    }
    float tot = lsum;
#pragma unroll
    for (int o = 16; o; o >>= 1) tot += __shfl_xor_sync(0xffffffffu, tot, o);
    float itot = __fdividef(1.0f, tot);

    float wn[6]; float ls2 = 0.0f;
#pragma unroll
    for (int q = 0; q < 6; ++q) { wn[q] = wr[q] * itot; ls2 += wn[q]; }
    float scs = ls2;
#pragma unroll
    for (int o = 1; o < 32; o <<= 1) {
        float t = __shfl_up_sync(0xffffffffu, scs, o);
        if (lane >= o) scs += t;
    }
    float base = __shfl_up_sync(0xffffffffu, scs, 1);
    if (lane == 0) base = 0.0f;
    float run = base;
#pragma unroll
    for (int q = 0; q < 6; ++q) { run += wn[q]; sCdf[warp][lane * 6 + q] = run; }
    // pad [192..255] with +inf so the bit-ladder needs no bounds check
    // (u < cdf[190] is guaranteed: strictly increasing cdf, r < 1)
    sCdf[warp][192 + lane] = 1e30f;
    sCdf[warp][224 + lane] = 1e30f;
    __syncwarp();

    const float cdfl = sCdf[warp][1];
    const float cdfh = sCdf[warp][190];

    // ---- importance sampling: unconditional branchless bit-ladder ----
    float zlf[4];
#pragma unroll
    for (int q = 0; q < 4; ++q) {
        int j = (lane << 2) + q;
        float r = tf_uniform((unsigned)(ray * NFINE + j));
        float u = (float)j * 0.0078125f + r * 0.0078125f;
        u = u * (cdfh - cdfl) + cdfl;
        int k = 0;
#pragma unroll
        for (int s = 128; s >= 1; s >>= 1) {
            int cand = k + s;
            if (cand <= 191 && sCdf[warp][cand] <= u) k = cand;
        }
        // cand<=191 is compile-time decidable per step after padding (only
        // s=128 path can exceed); ptxas folds most checks away.
        float cb = sCdf[warp][k], ca = sCdf[warp][k + 1];
        float tt = __fdividef(u - cb, ca - cb);
        float zb = zmid_c(k), za = zmid_c(k + 1);
        zlf[q] = zb + (za - zb) * tt;
    }

    // ---- fine pass: streamed features, f32x2 over j-pairs, split in 2 j-halves ----
    float sig[4], rr[4], rg[4], rb[4];
#pragma unroll
    for (int p = 0; p < 2; ++p) {
        const int q0 = 2 * p, q1 = 2 * p + 1;
        float z0 = fexp10(zlf[q0]), z1 = fexp10(zlf[q1]);
        float px0 = fmaf(rdx, z0, ox), py0 = fmaf(rdy, z0, oy), pz0 = fmaf(rdz, z0, oz);
        float px1 = fmaf(rdx, z1, ox), py1 = fmaf(rdy, z1, oy), pz1 = fmaf(rdz, z1, oz);
        mip_scale(px0, py0, pz0);
        mip_scale(px1, py1, pz1);

        float a0r = gbc2[0], a0g = gbc2[1], a0b = gbc2[2];
        float a1r = a0r, a1g = a0g, a1b = a0b;
        float sg0 = bd2v, sg1 = bd2v;

#pragma unroll
        for (int hh = 0; hh < 2; ++hh) {
            const int jb = hh << 4;                       // j base: 0 or 16
            u64 acc0p[8], acc1p[8];
            {
                u64 ndxp = pack2(ndx, ndx), ndyp = pack2(ndy, ndy), ndzp = pack2(ndz, ndz);
                const ulonglong2* b2  = (const ulonglong2*)&sBc1[jb];
                const ulonglong2* wx2 = (const ulonglong2*)&sWc1[1024 + jb];
                const ulonglong2* wy2 = (const ulonglong2*)&sWc1[1056 + jb];
                const ulonglong2* wz2 = (const ulonglong2*)&sWc1[1088 + jb];
#pragma unroll
                for (int g = 0; g < 4; ++g) {
                    ulonglong2 b  = b2[g];
                    ulonglong2 wx = wx2[g];
                    ulonglong2 wy = wy2[g];
                    ulonglong2 wz = wz2[g];
                    u64 va = b.x, vb = b.y;
                    fma2(va, ndxp, wx.x); fma2(vb, ndxp, wx.y);
                    fma2(va, ndyp, wy.x); fma2(vb, ndyp, wy.y);
                    fma2(va, ndzp, wz.x); fma2(vb, ndzp, wz.y);
                    acc0p[2 * g] = va; acc1p[2 * g] = va;
                    acc0p[2 * g + 1] = vb; acc1p[2 * g + 1] = vb;
                }
            }

#pragma unroll 4
            for (int c = 0; c < 32; ++c) {
                float4 wd = sWd1p[c];
                float t0 = fmaf(px0, wd.x, fmaf(py0, wd.y, fmaf(pz0, wd.z, wd.w)));
                float t1 = fmaf(px1, wd.x, fmaf(py1, wd.y, fmaf(pz1, wd.z, wd.w)));
                t0 = fmaxf(t0, 0.0f); t1 = fmaxf(t1, 0.0f);
                if (hh == 0) {
                    float v2 = sWd2[c];
                    sg0 = fmaf(t0, v2, sg0); sg1 = fmaf(t1, v2, sg1);
                }
                u64 t00 = pack2(t0, t0);
                u64 t11 = pack2(t1, t1);
                const ulonglong2* wc = (const ulonglong2*)&sWc1[c * 32 + jb];
#pragma unroll
                for (int g = 0; g < 4; ++g) {
                    ulonglong2 wv = wc[g];
                    fma2(acc0p[2 * g],     t00, wv.x);
                    fma2(acc0p[2 * g + 1], t00, wv.y);
                    fma2(acc1p[2 * g],     t11, wv.x);
                    fma2(acc1p[2 * g + 1], t11, wv.y);
                }
            }

            // layer2 partial for this half
#pragma unroll
            for (int g = 0; g < 4; ++g) {
                int j4 = jb + 4 * g;
                float4 u0 = *(const float4*)&sWc2c[0][j4];
                float4 u1 = *(const float4*)&sWc2c[1][j4];
                float4 u2 = *(const float4*)&sWc2c[2][j4];
                float h00, h01, h02, h03, h10, h11, h12, h13;
                unpack2(acc0p[2 * g],     h00, h01);
                unpack2(acc0p[2 * g + 1], h02, h03);
                unpack2(acc1p[2 * g],     h10, h11);
                unpack2(acc1p[2 * g + 1], h12, h13);
                h00 = fmaxf(h00, 0.0f); h01 = fmaxf(h01, 0.0f);
                h02 = fmaxf(h02, 0.0f); h03 = fmaxf(h03, 0.0f);
                h10 = fmaxf(h10, 0.0f); h11 = fmaxf(h11, 0.0f);
                h12 = fmaxf(h12, 0.0f); h13 = fmaxf(h13, 0.0f);
                a0r = fmaf(h00, u0.x, a0r); a0g = fmaf(h00, u1.x, a0g); a0b = fmaf(h00, u2.x, a0b);
                a1r = fmaf(h10, u0.x, a1r); a1g = fmaf(h10, u1.x, a1g); a1b = fmaf(h10, u2.x, a1b);
                a0r = fmaf(h01, u0.y, a0r); a0g = fmaf(h01, u1.y, a0g); a0b = fmaf(h01, u2.y, a0b);
                a1r = fmaf(h11, u0.y, a1r); a1g = fmaf(h11, u1.y, a1g); a1b = fmaf(h11, u2.y, a1b);
                a0r = fmaf(h02, u0.z, a0r); a0g = fmaf(h02, u1.z, a0g); a0b = fmaf(h02, u2.z, a0b);
                a1r = fmaf(h12, u0.z, a1r); a1g = fmaf(h12, u1.z, a1g); a1b = fmaf(h12, u2.z, a1b);
                a0r = fmaf(h03, u0.w, a0r); a0g = fmaf(h03, u1.w, a0g); a0b = fmaf(h03, u2.w, a0b);
                a1r = fmaf(h13, u0.w, a1r); a1g = fmaf(h13, u1.w, a1g); a1b = fmaf(h13, u2.w, a1b);
            }
        }

        sig[q0] = fsoftplus(sg0);
        sig[q1] = fsoftplus(sg1);
        rr[q0] = fsigmoid(a0r); rg[q0] = fsigmoid(a0g); rb[q0] = fsigmoid(a0b);
        rr[q1] = fsigmoid(a1r); rg[q1] = fsigmoid(a1g); rb[q1] = fsigmoid(a1b);
    }

    // ---- fine weights + accumulation ----
    float znx = __shfl_down_sync(0xffffffffu, zlf[0], 1);
    float dl[4];
    dl[0] = zlf[1] - zlf[0];
    dl[1] = zlf[2] - zlf[1];
    dl[2] = zlf[3] - zlf[2];
    dl[3] = (lane == 31) ? 0.0f : (znx - zlf[3]);

    float al[4], om2[4]; float lp = 1.0f;
#pragma unroll
    for (int q = 0; q < 4; ++q) {
        al[q] = 1.0f - fexp(-sig[q] * dl[q]);
        om2[q] = 1.0f - al[q];
        lp *= om2[q];
    }
    float scan2 = lp;
#pragma unroll
    for (int o = 1; o < 32; o <<= 1) {
        float t = __shfl_up_sync(0xffffffffu, scan2, o);
        if (lane >= o) scan2 *= t;
    }
    float T2 = __shfl_up_sync(0xffffffffu, scan2, 1);
    if (lane == 0) T2 = 1.0f;
    float w4[4];
#pragma unroll
    for (int q = 0; q < 4; ++q) { w4[q] = al[q] * T2; T2 *= om2[q]; }

    float ir = 0.0f, ig = 0.0f, ib = 0.0f, ivd = 0.0f, ws = 0.0f;
#pragma unroll
    for (int q = 0; q < 4; ++q) {
        ir = fmaf(w4[q], rr[q], ir);
        ig = fmaf(w4[q], rg[q], ig);
        ib = fmaf(w4[q], rb[q], ib);
        ivd = fmaf(w4[q], fexp10(-zlf[q]), ivd);
        ws  += w4[q];
    }
#pragma unroll
    for (int o = 16; o; o >>= 1) {
        ir  += __shfl_xor_sync(0xffffffffu, ir, o);
        ig  += __shfl_xor_sync(0xffffffffu, ig, o);
        ib  += __shfl_xor_sync(0xffffffffu, ib, o);
        ivd += __shfl_xor_sync(0xffffffffu, ivd, o);
        ws  += __shfl_xor_sync(0xffffffffu, ws, o);
    }

    // ---- stores ----
    *(float4*)(oW + (size_t)ray * NFINE + lane * 4) =
        make_float4(w4[0], w4[1], w4[2], w4[3]);
    *(float4*)(oZ + (size_t)ray * NFINE + lane * 4) =
        make_float4((zlf[0] + 1.0f) * 0.5f, (zlf[1] + 1.0f) * 0.5f,
                    (zlf[2] + 1.0f) * 0.5f, (zlf[3] + 1.0f) * 0.5f);

    if (lane == 0) {
        float oneMw = 1.0f - ws;
        oImg[ray * 3 + 0] = ir + oneMw * gbg[0];
        oImg[ray * 3 + 1] = ig + oneMw * gbg[1];
        oImg[ray * 3 + 2] = ib + oneMw * gbg[2];
        oInv[ray] = ivd;
    }
}

extern "C" void kernel_launch(void* const* d_in, const int* in_sizes, int n_in,
                              void* d_out, int out_size) {
    const float* h   = (const float*)d_in[1];
    const float* w   = (const float*)d_in[2];
    const float* K   = (const float*)d_in[3];
    const float* E   = (const float*)d_in[4];
    const float* bg  = (const float*)d_in[5];
    const float* Wd1 = (const float*)d_in[6];
    const float* bd1 = (const float*)d_in[7];
    const float* Wd2 = (const float*)d_in[8];
    const float* bd2 = (const float*)d_in[9];
    const float* Wc1 = (const float*)d_in[10];
    const float* bc1 = (const float*)d_in[11];
    const float* Wc2 = (const float*)d_in[12];
    const float* bc2 = (const float*)d_in[13];

    float* out   = (float*)d_out;
    float* oImg  = out;
    float* oW    = out + NRAYS * 3;
    float* oZ    = oW + (size_t)NRAYS * NFINE;
    float* oInv  = oZ + (size_t)NRAYS * NFINE;

    nerf_fused<<<NRAYS / 4, 128>>>(h, w, K, E, bg,
                                   Wd1, bd1, Wd2, bd2,
                                   Wc1, bc1, Wc2, bc2,
                                   oImg, oW, oZ, oInv);
}